// round 1
// baseline (speedup 1.0000x reference)
#include <cuda_runtime.h>
#include <math.h>

#define B_  4
#define S_  2048
#define D_  1024
#define H_  16
#define HD_ 64
#define M_  (B_ * S_)   // 8192

// Scratch (allocation-free rule: __device__ globals)
__device__ float g_qkv[(size_t)M_ * 3 * D_];   // [B*S, 3D] = 96 MB
__device__ float g_attn[(size_t)M_ * D_];      // [B*S, D]  = 32 MB

// ---------------------------------------------------------------------------
// SGEMM + bias: C[M,N] = A[M,K] @ W[K,N] + bias[N]
// 128x128 block tile, BK=16, 256 threads, 8x8 per thread.
// ---------------------------------------------------------------------------
__global__ __launch_bounds__(256) void sgemm_bias(
    const float* __restrict__ A, const float* __restrict__ W,
    const float* __restrict__ bias, float* __restrict__ C,
    int M, int N, int K)
{
    __shared__ float As[16][128];   // A tile, transposed: As[k][m]
    __shared__ float Bs[16][128];   // W tile: Bs[k][n]

    const int tid = threadIdx.x;
    const int bx = blockIdx.x, by = blockIdx.y;
    const int tx = tid & 15, ty = tid >> 4;
    const int cr = ty * 8, cc = tx * 8;

    const float* Ab = A + (size_t)by * 128 * K;
    const float* Wb = W + (size_t)bx * 128;

    const int a_r = tid >> 2;          // 0..63
    const int a_c = (tid & 3) << 2;    // 0,4,8,12
    const int b_r = tid >> 5;          // 0..7
    const int b_c = (tid & 31) << 2;   // 0..124

    float acc[8][8];
#pragma unroll
    for (int i = 0; i < 8; i++)
#pragma unroll
        for (int j = 0; j < 8; j++) acc[i][j] = 0.f;

    for (int k0 = 0; k0 < K; k0 += 16) {
#pragma unroll
        for (int i = 0; i < 2; i++) {
            int r = a_r + i * 64;
            float4 v = *(const float4*)(Ab + (size_t)r * K + k0 + a_c);
            As[a_c + 0][r] = v.x; As[a_c + 1][r] = v.y;
            As[a_c + 2][r] = v.z; As[a_c + 3][r] = v.w;
        }
#pragma unroll
        for (int i = 0; i < 2; i++) {
            int r = b_r + i * 8;
            *(float4*)&Bs[r][b_c] = *(const float4*)(Wb + (size_t)(k0 + r) * N + b_c);
        }
        __syncthreads();

#pragma unroll
        for (int k = 0; k < 16; k++) {
            float a[8], bb[8];
            *(float4*)&a[0]  = *(float4*)&As[k][cr];
            *(float4*)&a[4]  = *(float4*)&As[k][cr + 4];
            *(float4*)&bb[0] = *(float4*)&Bs[k][cc];
            *(float4*)&bb[4] = *(float4*)&Bs[k][cc + 4];
#pragma unroll
            for (int i = 0; i < 8; i++)
#pragma unroll
                for (int j = 0; j < 8; j++)
                    acc[i][j] += a[i] * bb[j];
        }
        __syncthreads();
    }

#pragma unroll
    for (int i = 0; i < 8; i++) {
        size_t row = (size_t)(by * 128 + cr + i) * N + bx * 128;
#pragma unroll
        for (int j = 0; j < 8; j += 4) {
            int c = bx * 128 + cc + j;
            float4 v;
            v.x = acc[i][j + 0] + bias[c + 0];
            v.y = acc[i][j + 1] + bias[c + 1];
            v.z = acc[i][j + 2] + bias[c + 2];
            v.w = acc[i][j + 3] + bias[c + 3];
            *(float4*)(C + row + cc + j) = v;
        }
    }
}

// ---------------------------------------------------------------------------
// Flash attention: one block = 64 query rows of one (b,h).
// qkv layout: [(b*S+s)*3*D + part*D + h*64 + hd]
// Output g_attn layout: [B,S,D] with d = h*64 + hd (ready for proj GEMM).
// smem: Qt [hd][q] 16K, KtPs (K^T [hd][kv], then P [q][kv]) 16K, Vs [kv][hd] 16K
// ---------------------------------------------------------------------------
__global__ __launch_bounds__(256) void attn_kernel(const float* __restrict__ qkv,
                                                   float* __restrict__ out)
{
    __shared__ float Qt[64][64];
    __shared__ float KtPs[64][64];
    __shared__ float Vs[64][64];

    const int tid = threadIdx.x;
    const int tx = tid & 15, ty = tid >> 4;
    const int bh = blockIdx.y;
    const int b = bh >> 4, h = bh & 15;
    const int q0 = blockIdx.x * 64;

    const size_t row3D = 3 * (size_t)D_;
    const size_t hoff = (size_t)h * HD_;

    // Load Q tile transposed (HD-major)
#pragma unroll
    for (int it = 0; it < 4; it++) {
        int idx = it * 256 + tid;
        int r = idx >> 4;             // q row in tile
        int c = (idx & 15) << 2;      // hd start
        float4 v = *(const float4*)(qkv + (size_t)(b * S_ + q0 + r) * row3D + hoff + c);
        Qt[c + 0][r] = v.x; Qt[c + 1][r] = v.y;
        Qt[c + 2][r] = v.z; Qt[c + 3][r] = v.w;
    }

    float m_st[4], l_st[4], acc[4][4];
#pragma unroll
    for (int i = 0; i < 4; i++) {
        m_st[i] = -3.0e38f;
        l_st[i] = 0.f;
#pragma unroll
        for (int j = 0; j < 4; j++) acc[i][j] = 0.f;
    }
    const float scale = 0.125f;  // 1/sqrt(64)

    for (int kv0 = 0; kv0 < S_; kv0 += 64) {
        __syncthreads();  // prior-iter PV readers done before overwriting KtPs/Vs
#pragma unroll
        for (int it = 0; it < 4; it++) {
            int idx = it * 256 + tid;
            int r = idx >> 4;
            int c = (idx & 15) << 2;
            size_t rowbase = (size_t)(b * S_ + kv0 + r) * row3D + hoff;
            float4 kv4 = *(const float4*)(qkv + rowbase + D_ + c);
            KtPs[c + 0][r] = kv4.x; KtPs[c + 1][r] = kv4.y;
            KtPs[c + 2][r] = kv4.z; KtPs[c + 3][r] = kv4.w;
            *(float4*)&Vs[r][c] = *(const float4*)(qkv + rowbase + 2 * D_ + c);
        }
        __syncthreads();

        // S tile: s[i][j] = sum_k Q[q][k] * K[kv][k]
        float s[4][4];
#pragma unroll
        for (int i = 0; i < 4; i++)
#pragma unroll
            for (int j = 0; j < 4; j++) s[i][j] = 0.f;

#pragma unroll
        for (int k = 0; k < 64; k++) {
            float4 qa = *(float4*)&Qt[k][ty * 4];
            float4 kb = *(float4*)&KtPs[k][tx * 4];
            float qv[4] = {qa.x, qa.y, qa.z, qa.w};
            float kv_[4] = {kb.x, kb.y, kb.z, kb.w};
#pragma unroll
            for (int i = 0; i < 4; i++)
#pragma unroll
                for (int j = 0; j < 4; j++)
                    s[i][j] += qv[i] * kv_[j];
        }

        // Online softmax (per-q-row state, replicated across tx group of 16)
        float rmax[4];
#pragma unroll
        for (int i = 0; i < 4; i++) {
            s[i][0] *= scale; s[i][1] *= scale; s[i][2] *= scale; s[i][3] *= scale;
            rmax[i] = fmaxf(fmaxf(s[i][0], s[i][1]), fmaxf(s[i][2], s[i][3]));
        }
#pragma unroll
        for (int off = 8; off >= 1; off >>= 1)
#pragma unroll
            for (int i = 0; i < 4; i++)
                rmax[i] = fmaxf(rmax[i], __shfl_xor_sync(0xffffffffu, rmax[i], off, 16));

        float alpha[4], rsum[4];
#pragma unroll
        for (int i = 0; i < 4; i++) {
            float mn = fmaxf(m_st[i], rmax[i]);
            alpha[i] = __expf(m_st[i] - mn);
            m_st[i] = mn;
            rsum[i] = 0.f;
#pragma unroll
            for (int j = 0; j < 4; j++) {
                s[i][j] = __expf(s[i][j] - mn);
                rsum[i] += s[i][j];
            }
        }
#pragma unroll
        for (int off = 8; off >= 1; off >>= 1)
#pragma unroll
            for (int i = 0; i < 4; i++)
                rsum[i] += __shfl_xor_sync(0xffffffffu, rsum[i], off, 16);
#pragma unroll
        for (int i = 0; i < 4; i++) {
            l_st[i] = l_st[i] * alpha[i] + rsum[i];
#pragma unroll
            for (int j = 0; j < 4; j++) acc[i][j] *= alpha[i];
        }

        __syncthreads();  // everyone done reading K^T; reuse buffer for P
#pragma unroll
        for (int i = 0; i < 4; i++) {
            float4 p = make_float4(s[i][0], s[i][1], s[i][2], s[i][3]);
            *(float4*)&KtPs[ty * 4 + i][tx * 4] = p;
        }
        __syncthreads();

        // O += P @ V
#pragma unroll
        for (int c = 0; c < 64; c += 4) {
            float pr[4][4];
#pragma unroll
            for (int i = 0; i < 4; i++)
                *(float4*)pr[i] = *(float4*)&KtPs[ty * 4 + i][c];
#pragma unroll
            for (int u = 0; u < 4; u++) {
                float4 vv = *(float4*)&Vs[c + u][tx * 4];
#pragma unroll
                for (int i = 0; i < 4; i++) {
                    acc[i][0] += pr[i][u] * vv.x;
                    acc[i][1] += pr[i][u] * vv.y;
                    acc[i][2] += pr[i][u] * vv.z;
                    acc[i][3] += pr[i][u] * vv.w;
                }
            }
        }
    }

#pragma unroll
    for (int i = 0; i < 4; i++) {
        float inv = 1.f / l_st[i];
        float4 o;
        o.x = acc[i][0] * inv; o.y = acc[i][1] * inv;
        o.z = acc[i][2] * inv; o.w = acc[i][3] * inv;
        *(float4*)(out + (size_t)(b * S_ + q0 + ty * 4 + i) * D_ + hoff + tx * 4) = o;
    }
}

// ---------------------------------------------------------------------------
extern "C" void kernel_launch(void* const* d_in, const int* in_sizes, int n_in,
                              void* d_out, int out_size)
{
    const float* x      = (const float*)d_in[0];
    const float* w_qkv  = (const float*)d_in[1];
    const float* b_qkv  = (const float*)d_in[2];
    const float* w_proj = (const float*)d_in[3];
    const float* b_proj = (const float*)d_in[4];
    float* out = (float*)d_out;

    float *qkv_ptr, *attn_ptr;
    cudaGetSymbolAddress((void**)&qkv_ptr,  g_qkv);
    cudaGetSymbolAddress((void**)&attn_ptr, g_attn);

    // 1) QKV projection: [8192,1024] @ [1024,3072] + bias
    sgemm_bias<<<dim3(3 * D_ / 128, M_ / 128), 256>>>(
        x, w_qkv, b_qkv, qkv_ptr, M_, 3 * D_, D_);

    // 2) Attention: grid (q tiles, b*h)
    attn_kernel<<<dim3(S_ / 64, B_ * H_), 256>>>(qkv_ptr, attn_ptr);

    // 3) Output projection: [8192,1024] @ [1024,1024] + bias
    sgemm_bias<<<dim3(D_ / 128, M_ / 128), 256>>>(
        attn_ptr, w_proj, b_proj, out, M_, D_, D_);
}

// round 3
// speedup vs baseline: 1.3498x; 1.3498x over previous
#include <cuda_runtime.h>
#include <cstdint>
#include <math.h>

#define B_  4
#define S_  2048
#define D_  1024
#define H_  16
#define HD_ 64
#define M_  (B_ * S_)   // 8192

__device__ float g_qkv[(size_t)M_ * 3 * D_];   // [B*S, 3D]
__device__ float g_attn[(size_t)M_ * D_];      // [B*S, D]

__device__ __forceinline__ uint32_t f2tf32(float f) {
    uint32_t u;
    asm("cvt.rna.tf32.f32 %0, %1;" : "=r"(u) : "f"(f));
    return u;
}

__device__ __forceinline__ void mma_tf32(float& d0, float& d1, float& d2, float& d3,
                                         uint32_t a0, uint32_t a1, uint32_t a2, uint32_t a3,
                                         uint32_t b0, uint32_t b1) {
    asm volatile(
        "mma.sync.aligned.m16n8k8.row.col.f32.tf32.tf32.f32 "
        "{%0,%1,%2,%3}, {%4,%5,%6,%7}, {%8,%9}, {%0,%1,%2,%3};"
        : "+f"(d0), "+f"(d1), "+f"(d2), "+f"(d3)
        : "r"(a0), "r"(a1), "r"(a2), "r"(a3), "r"(b0), "r"(b1));
}

// ---------------------------------------------------------------------------
// TF32 mma.sync GEMM + bias: C[M,N] = A[M,K] @ W[K,N] + bias[N]
// CTA 128x128, BK=32, 256 threads (8 warps, 2x4), warp tile 64x32.
// Smem: As[2][128][36] (pad->frag banks 4g+t distinct), Bs[2][32][136] (8t+c).
// Double buffered via register staging (LDG f4 -> cvt tf32 -> STS).
// ---------------------------------------------------------------------------
#define AS_STRIDE 36
#define BS_STRIDE 136
#define AS_TILE   (128 * AS_STRIDE)
#define BS_TILE   (32 * BS_STRIDE)
#define SMEM_FLOATS (2 * AS_TILE + 2 * BS_TILE)

__global__ __launch_bounds__(256) void gemm_mma(
    const float* __restrict__ A, const float* __restrict__ W,
    const float* __restrict__ bias, float* __restrict__ C,
    int N, int K)
{
    extern __shared__ __align__(16) float sm[];
    uint32_t* sA = (uint32_t*)sm;                 // [2][AS_TILE]
    uint32_t* sB = (uint32_t*)(sm + 2 * AS_TILE); // [2][BS_TILE]

    const int tid = threadIdx.x;
    const int lane = tid & 31;
    const int wid = tid >> 5;
    const int wm = wid & 1;       // 0..1 -> 64 rows each
    const int wn = wid >> 1;      // 0..3 -> 32 cols each
    const int bx = blockIdx.x, by = blockIdx.y;

    const int g = lane >> 2;      // 0..7
    const int t = lane & 3;       // 0..3

    // Fill mappings
    const int a_row = tid >> 1;               // wrong granularity; use chunk math below
    (void)a_row;
    // A: 1024 float4-chunks/stage: idx = tid + i*256; row=idx>>3, col=(idx&7)*4
    // B: 1024 float4-chunks/stage: idx = tid + i*256; row=idx>>5, col=(idx&31)*4
    const float* Abase = A + (size_t)by * 128 * K;
    const float* Wbase = W + (size_t)bx * 128;

    float4 ra[4], rb[4];

    // ---- prologue: load + store stage 0 ----
#pragma unroll
    for (int i = 0; i < 4; i++) {
        int idx = tid + i * 256;
        ra[i] = *(const float4*)(Abase + (size_t)(idx >> 3) * K + ((idx & 7) << 2));
        rb[i] = *(const float4*)(Wbase + (size_t)(idx >> 5) * N + ((idx & 31) << 2));
    }
#pragma unroll
    for (int i = 0; i < 4; i++) {
        int idx = tid + i * 256;
        uint32_t* pa = sA + (idx >> 3) * AS_STRIDE + ((idx & 7) << 2);
        pa[0] = f2tf32(ra[i].x); pa[1] = f2tf32(ra[i].y);
        pa[2] = f2tf32(ra[i].z); pa[3] = f2tf32(ra[i].w);
        uint32_t* pb = sB + (idx >> 5) * BS_STRIDE + ((idx & 31) << 2);
        pb[0] = f2tf32(rb[i].x); pb[1] = f2tf32(rb[i].y);
        pb[2] = f2tf32(rb[i].z); pb[3] = f2tf32(rb[i].w);
    }
    __syncthreads();

    float acc[4][4][4];
#pragma unroll
    for (int mt = 0; mt < 4; mt++)
#pragma unroll
        for (int nt = 0; nt < 4; nt++)
#pragma unroll
            for (int r = 0; r < 4; r++) acc[mt][nt][r] = 0.f;

    const int nstages = K >> 5;   // K/32
    for (int s = 0; s < nstages; s++) {
        const int buf = s & 1;
        // prefetch next stage into regs
        if (s + 1 < nstages) {
            const int k0 = (s + 1) << 5;
#pragma unroll
            for (int i = 0; i < 4; i++) {
                int idx = tid + i * 256;
                ra[i] = *(const float4*)(Abase + (size_t)(idx >> 3) * K + k0 + ((idx & 7) << 2));
                rb[i] = *(const float4*)(Wbase + (size_t)((idx >> 5) + k0) * N + ((idx & 31) << 2));
            }
        }

        const uint32_t* cA = sA + buf * AS_TILE;
        const uint32_t* cB = sB + buf * BS_TILE;

#pragma unroll
        for (int ks = 0; ks < 4; ks++) {
            const int k0 = ks << 3;
            uint32_t af[4][4], bf[4][2];
#pragma unroll
            for (int mt = 0; mt < 4; mt++) {
                const uint32_t* base = cA + (wm * 64 + mt * 16 + g) * AS_STRIDE + k0 + t;
                af[mt][0] = base[0];
                af[mt][1] = base[8 * AS_STRIDE];
                af[mt][2] = base[4];
                af[mt][3] = base[8 * AS_STRIDE + 4];
            }
#pragma unroll
            for (int nt = 0; nt < 4; nt++) {
                const uint32_t* base = cB + (k0 + t) * BS_STRIDE + wn * 32 + nt * 8 + g;
                bf[nt][0] = base[0];
                bf[nt][1] = base[4 * BS_STRIDE];
            }
#pragma unroll
            for (int mt = 0; mt < 4; mt++)
#pragma unroll
                for (int nt = 0; nt < 4; nt++)
                    mma_tf32(acc[mt][nt][0], acc[mt][nt][1], acc[mt][nt][2], acc[mt][nt][3],
                             af[mt][0], af[mt][1], af[mt][2], af[mt][3],
                             bf[nt][0], bf[nt][1]);
        }
        __syncthreads();   // all reads of buf (and buf^1 from s-1) done

        if (s + 1 < nstages) {
            const int nbuf = (s + 1) & 1;
            uint32_t* dA = sA + nbuf * AS_TILE;
            uint32_t* dB = sB + nbuf * BS_TILE;
#pragma unroll
            for (int i = 0; i < 4; i++) {
                int idx = tid + i * 256;
                uint32_t* pa = dA + (idx >> 3) * AS_STRIDE + ((idx & 7) << 2);
                pa[0] = f2tf32(ra[i].x); pa[1] = f2tf32(ra[i].y);
                pa[2] = f2tf32(ra[i].z); pa[3] = f2tf32(ra[i].w);
                uint32_t* pb = dB + (idx >> 5) * BS_STRIDE + ((idx & 31) << 2);
                pb[0] = f2tf32(rb[i].x); pb[1] = f2tf32(rb[i].y);
                pb[2] = f2tf32(rb[i].z); pb[3] = f2tf32(rb[i].w);
            }
            __syncthreads();
        }
    }

    // ---- epilogue: direct global stores with bias ----
#pragma unroll
    for (int nt = 0; nt < 4; nt++) {
        const int c = bx * 128 + wn * 32 + nt * 8 + 2 * t;
        const float bx0 = bias[c], bx1 = bias[c + 1];
#pragma unroll
        for (int mt = 0; mt < 4; mt++) {
            const int r0 = by * 128 + wm * 64 + mt * 16 + g;
            float2 v0 = make_float2(acc[mt][nt][0] + bx0, acc[mt][nt][1] + bx1);
            float2 v1 = make_float2(acc[mt][nt][2] + bx0, acc[mt][nt][3] + bx1);
            *(float2*)(C + (size_t)r0 * N + c)       = v0;
            *(float2*)(C + (size_t)(r0 + 8) * N + c) = v1;
        }
    }
}

// ---------------------------------------------------------------------------
// Flash attention (FFMA, unchanged from passing R1)
// ---------------------------------------------------------------------------
__global__ __launch_bounds__(256) void attn_kernel(const float* __restrict__ qkv,
                                                   float* __restrict__ out)
{
    __shared__ float Qt[64][64];
    __shared__ float KtPs[64][64];
    __shared__ float Vs[64][64];

    const int tid = threadIdx.x;
    const int tx = tid & 15, ty = tid >> 4;
    const int bh = blockIdx.y;
    const int b = bh >> 4, h = bh & 15;
    const int q0 = blockIdx.x * 64;

    const size_t row3D = 3 * (size_t)D_;
    const size_t hoff = (size_t)h * HD_;

#pragma unroll
    for (int it = 0; it < 4; it++) {
        int idx = it * 256 + tid;
        int r = idx >> 4;
        int c = (idx & 15) << 2;
        float4 v = *(const float4*)(qkv + (size_t)(b * S_ + q0 + r) * row3D + hoff + c);
        Qt[c + 0][r] = v.x; Qt[c + 1][r] = v.y;
        Qt[c + 2][r] = v.z; Qt[c + 3][r] = v.w;
    }

    float m_st[4], l_st[4], acc[4][4];
#pragma unroll
    for (int i = 0; i < 4; i++) {
        m_st[i] = -3.0e38f;
        l_st[i] = 0.f;
#pragma unroll
        for (int j = 0; j < 4; j++) acc[i][j] = 0.f;
    }
    const float scale = 0.125f;

    for (int kv0 = 0; kv0 < S_; kv0 += 64) {
        __syncthreads();
#pragma unroll
        for (int it = 0; it < 4; it++) {
            int idx = it * 256 + tid;
            int r = idx >> 4;
            int c = (idx & 15) << 2;
            size_t rowbase = (size_t)(b * S_ + kv0 + r) * row3D + hoff;
            float4 kv4 = *(const float4*)(qkv + rowbase + D_ + c);
            KtPs[c + 0][r] = kv4.x; KtPs[c + 1][r] = kv4.y;
            KtPs[c + 2][r] = kv4.z; KtPs[c + 3][r] = kv4.w;
            *(float4*)&Vs[r][c] = *(const float4*)(qkv + rowbase + 2 * D_ + c);
        }
        __syncthreads();

        float s[4][4];
#pragma unroll
        for (int i = 0; i < 4; i++)
#pragma unroll
            for (int j = 0; j < 4; j++) s[i][j] = 0.f;

#pragma unroll
        for (int k = 0; k < 64; k++) {
            float4 qa = *(float4*)&Qt[k][ty * 4];
            float4 kb = *(float4*)&KtPs[k][tx * 4];
            float qv[4] = {qa.x, qa.y, qa.z, qa.w};
            float kv_[4] = {kb.x, kb.y, kb.z, kb.w};
#pragma unroll
            for (int i = 0; i < 4; i++)
#pragma unroll
                for (int j = 0; j < 4; j++)
                    s[i][j] += qv[i] * kv_[j];
        }

        float rmax[4];
#pragma unroll
        for (int i = 0; i < 4; i++) {
            s[i][0] *= scale; s[i][1] *= scale; s[i][2] *= scale; s[i][3] *= scale;
            rmax[i] = fmaxf(fmaxf(s[i][0], s[i][1]), fmaxf(s[i][2], s[i][3]));
        }
#pragma unroll
        for (int off = 8; off >= 1; off >>= 1)
#pragma unroll
            for (int i = 0; i < 4; i++)
                rmax[i] = fmaxf(rmax[i], __shfl_xor_sync(0xffffffffu, rmax[i], off, 16));

        float alpha[4], rsum[4];
#pragma unroll
        for (int i = 0; i < 4; i++) {
            float mn = fmaxf(m_st[i], rmax[i]);
            alpha[i] = __expf(m_st[i] - mn);
            m_st[i] = mn;
            rsum[i] = 0.f;
#pragma unroll
            for (int j = 0; j < 4; j++) {
                s[i][j] = __expf(s[i][j] - mn);
                rsum[i] += s[i][j];
            }
        }
#pragma unroll
        for (int off = 8; off >= 1; off >>= 1)
#pragma unroll
            for (int i = 0; i < 4; i++)
                rsum[i] += __shfl_xor_sync(0xffffffffu, rsum[i], off, 16);
#pragma unroll
        for (int i = 0; i < 4; i++) {
            l_st[i] = l_st[i] * alpha[i] + rsum[i];
#pragma unroll
            for (int j = 0; j < 4; j++) acc[i][j] *= alpha[i];
        }

        __syncthreads();
#pragma unroll
        for (int i = 0; i < 4; i++) {
            float4 p = make_float4(s[i][0], s[i][1], s[i][2], s[i][3]);
            *(float4*)&KtPs[ty * 4 + i][tx * 4] = p;
        }
        __syncthreads();

#pragma unroll
        for (int c = 0; c < 64; c += 4) {
            float pr[4][4];
#pragma unroll
            for (int i = 0; i < 4; i++)
                *(float4*)pr[i] = *(float4*)&KtPs[ty * 4 + i][c];
#pragma unroll
            for (int u = 0; u < 4; u++) {
                float4 vv = *(float4*)&Vs[c + u][tx * 4];
#pragma unroll
                for (int i = 0; i < 4; i++) {
                    acc[i][0] += pr[i][u] * vv.x;
                    acc[i][1] += pr[i][u] * vv.y;
                    acc[i][2] += pr[i][u] * vv.z;
                    acc[i][3] += pr[i][u] * vv.w;
                }
            }
        }
    }

#pragma unroll
    for (int i = 0; i < 4; i++) {
        float inv = 1.f / l_st[i];
        float4 o;
        o.x = acc[i][0] * inv; o.y = acc[i][1] * inv;
        o.z = acc[i][2] * inv; o.w = acc[i][3] * inv;
        *(float4*)(out + (size_t)(b * S_ + q0 + ty * 4 + i) * D_ + hoff + tx * 4) = o;
    }
}

// ---------------------------------------------------------------------------
extern "C" void kernel_launch(void* const* d_in, const int* in_sizes, int n_in,
                              void* d_out, int out_size)
{
    const float* x      = (const float*)d_in[0];
    const float* w_qkv  = (const float*)d_in[1];
    const float* b_qkv  = (const float*)d_in[2];
    const float* w_proj = (const float*)d_in[3];
    const float* b_proj = (const float*)d_in[4];
    float* out = (float*)d_out;

    float *qkv_ptr, *attn_ptr;
    cudaGetSymbolAddress((void**)&qkv_ptr,  g_qkv);
    cudaGetSymbolAddress((void**)&attn_ptr, g_attn);

    const int smem_bytes = SMEM_FLOATS * 4;  // 71680
    static bool attr_set = false;
    if (!attr_set) {
        cudaFuncSetAttribute(gemm_mma, cudaFuncAttributeMaxDynamicSharedMemorySize,
                             smem_bytes);
        attr_set = true;
    }

    // 1) QKV projection: [8192,1024] @ [1024,3072] + bias (tf32 mma.sync)
    gemm_mma<<<dim3(3 * D_ / 128, M_ / 128), 256, smem_bytes>>>(
        x, w_qkv, b_qkv, qkv_ptr, 3 * D_, D_);

    // 2) Attention (FFMA flash)
    attn_kernel<<<dim3(S_ / 64, B_ * H_), 256>>>(qkv_ptr, attn_ptr);

    // 3) Output projection: [8192,1024] @ [1024,1024] + bias (tf32 mma.sync)
    gemm_mma<<<dim3(D_ / 128, M_ / 128), 256, smem_bytes>>>(
        attn_ptr, w_proj, b_proj, out, D_, D_);
}

// round 4
// speedup vs baseline: 2.9467x; 2.1831x over previous
#include <cuda_runtime.h>
#include <cstdint>
#include <math.h>

#define B_  4
#define S_  2048
#define D_  1024
#define H_  16
#define HD_ 64
#define M_  (B_ * S_)   // 8192

__device__ float g_qkv[(size_t)M_ * 3 * D_];   // [B*S, 3D]
__device__ float g_attn[(size_t)M_ * D_];      // [B*S, D]

__device__ __forceinline__ uint32_t f2tf32(float f) {
    uint32_t u;
    asm("cvt.rna.tf32.f32 %0, %1;" : "=r"(u) : "f"(f));
    return u;
}

__device__ __forceinline__ void mma_tf32(float& d0, float& d1, float& d2, float& d3,
                                         uint32_t a0, uint32_t a1, uint32_t a2, uint32_t a3,
                                         uint32_t b0, uint32_t b1) {
    asm volatile(
        "mma.sync.aligned.m16n8k8.row.col.f32.tf32.tf32.f32 "
        "{%0,%1,%2,%3}, {%4,%5,%6,%7}, {%8,%9}, {%0,%1,%2,%3};"
        : "+f"(d0), "+f"(d1), "+f"(d2), "+f"(d3)
        : "r"(a0), "r"(a1), "r"(a2), "r"(a3), "r"(b0), "r"(b1));
}

// ---------------------------------------------------------------------------
// TF32 mma.sync GEMM + bias (unchanged from passing R3)
// ---------------------------------------------------------------------------
#define AS_STRIDE 36
#define BS_STRIDE 136
#define AS_TILE   (128 * AS_STRIDE)
#define BS_TILE   (32 * BS_STRIDE)
#define SMEM_FLOATS (2 * AS_TILE + 2 * BS_TILE)

__global__ __launch_bounds__(256) void gemm_mma(
    const float* __restrict__ A, const float* __restrict__ W,
    const float* __restrict__ bias, float* __restrict__ C,
    int N, int K)
{
    extern __shared__ __align__(16) float sm[];
    uint32_t* sA = (uint32_t*)sm;                 // [2][AS_TILE]
    uint32_t* sB = (uint32_t*)(sm + 2 * AS_TILE); // [2][BS_TILE]

    const int tid = threadIdx.x;
    const int lane = tid & 31;
    const int wid = tid >> 5;
    const int wm = wid & 1;
    const int wn = wid >> 1;
    const int bx = blockIdx.x, by = blockIdx.y;

    const int g = lane >> 2;
    const int t = lane & 3;

    const float* Abase = A + (size_t)by * 128 * K;
    const float* Wbase = W + (size_t)bx * 128;

    float4 ra[4], rb[4];

#pragma unroll
    for (int i = 0; i < 4; i++) {
        int idx = tid + i * 256;
        ra[i] = *(const float4*)(Abase + (size_t)(idx >> 3) * K + ((idx & 7) << 2));
        rb[i] = *(const float4*)(Wbase + (size_t)(idx >> 5) * N + ((idx & 31) << 2));
    }
#pragma unroll
    for (int i = 0; i < 4; i++) {
        int idx = tid + i * 256;
        uint32_t* pa = sA + (idx >> 3) * AS_STRIDE + ((idx & 7) << 2);
        pa[0] = f2tf32(ra[i].x); pa[1] = f2tf32(ra[i].y);
        pa[2] = f2tf32(ra[i].z); pa[3] = f2tf32(ra[i].w);
        uint32_t* pb = sB + (idx >> 5) * BS_STRIDE + ((idx & 31) << 2);
        pb[0] = f2tf32(rb[i].x); pb[1] = f2tf32(rb[i].y);
        pb[2] = f2tf32(rb[i].z); pb[3] = f2tf32(rb[i].w);
    }
    __syncthreads();

    float acc[4][4][4];
#pragma unroll
    for (int mt = 0; mt < 4; mt++)
#pragma unroll
        for (int nt = 0; nt < 4; nt++)
#pragma unroll
            for (int r = 0; r < 4; r++) acc[mt][nt][r] = 0.f;

    const int nstages = K >> 5;
    for (int s = 0; s < nstages; s++) {
        const int buf = s & 1;
        if (s + 1 < nstages) {
            const int k0 = (s + 1) << 5;
#pragma unroll
            for (int i = 0; i < 4; i++) {
                int idx = tid + i * 256;
                ra[i] = *(const float4*)(Abase + (size_t)(idx >> 3) * K + k0 + ((idx & 7) << 2));
                rb[i] = *(const float4*)(Wbase + (size_t)((idx >> 5) + k0) * N + ((idx & 31) << 2));
            }
        }

        const uint32_t* cA = sA + buf * AS_TILE;
        const uint32_t* cB = sB + buf * BS_TILE;

#pragma unroll
        for (int ks = 0; ks < 4; ks++) {
            const int k0 = ks << 3;
            uint32_t af[4][4], bf[4][2];
#pragma unroll
            for (int mt = 0; mt < 4; mt++) {
                const uint32_t* base = cA + (wm * 64 + mt * 16 + g) * AS_STRIDE + k0 + t;
                af[mt][0] = base[0];
                af[mt][1] = base[8 * AS_STRIDE];
                af[mt][2] = base[4];
                af[mt][3] = base[8 * AS_STRIDE + 4];
            }
#pragma unroll
            for (int nt = 0; nt < 4; nt++) {
                const uint32_t* base = cB + (k0 + t) * BS_STRIDE + wn * 32 + nt * 8 + g;
                bf[nt][0] = base[0];
                bf[nt][1] = base[4 * BS_STRIDE];
            }
#pragma unroll
            for (int mt = 0; mt < 4; mt++)
#pragma unroll
                for (int nt = 0; nt < 4; nt++)
                    mma_tf32(acc[mt][nt][0], acc[mt][nt][1], acc[mt][nt][2], acc[mt][nt][3],
                             af[mt][0], af[mt][1], af[mt][2], af[mt][3],
                             bf[nt][0], bf[nt][1]);
        }
        __syncthreads();

        if (s + 1 < nstages) {
            const int nbuf = (s + 1) & 1;
            uint32_t* dA = sA + nbuf * AS_TILE;
            uint32_t* dB = sB + nbuf * BS_TILE;
#pragma unroll
            for (int i = 0; i < 4; i++) {
                int idx = tid + i * 256;
                uint32_t* pa = dA + (idx >> 3) * AS_STRIDE + ((idx & 7) << 2);
                pa[0] = f2tf32(ra[i].x); pa[1] = f2tf32(ra[i].y);
                pa[2] = f2tf32(ra[i].z); pa[3] = f2tf32(ra[i].w);
                uint32_t* pb = dB + (idx >> 5) * BS_STRIDE + ((idx & 31) << 2);
                pb[0] = f2tf32(rb[i].x); pb[1] = f2tf32(rb[i].y);
                pb[2] = f2tf32(rb[i].z); pb[3] = f2tf32(rb[i].w);
            }
            __syncthreads();
        }
    }

#pragma unroll
    for (int nt = 0; nt < 4; nt++) {
        const int c = bx * 128 + wn * 32 + nt * 8 + 2 * t;
        const float bx0 = bias[c], bx1 = bias[c + 1];
#pragma unroll
        for (int mt = 0; mt < 4; mt++) {
            const int r0 = by * 128 + wm * 64 + mt * 16 + g;
            float2 v0 = make_float2(acc[mt][nt][0] + bx0, acc[mt][nt][1] + bx1);
            float2 v1 = make_float2(acc[mt][nt][2] + bx0, acc[mt][nt][3] + bx1);
            *(float2*)(C + (size_t)r0 * N + c)       = v0;
            *(float2*)(C + (size_t)(r0 + 8) * N + c) = v1;
        }
    }
}

// ---------------------------------------------------------------------------
// TF32 mma.sync flash attention.
// Block = 128 threads (4 warps) = 64 query rows of one (b,h); warp owns 16 rows.
// Q pre-scaled by 1/8, tf32, kept in register A-frags for all KV tiles.
// K tile: sK[64][68] (QK B-frag banks 4g+t, conflict-free)
// V tile: sV[64][72] (PV B-frag banks 8t+g, conflict-free)
// P converted C-layout -> A-layout via quad shuffles (no smem round-trip).
// ---------------------------------------------------------------------------
#define KS_ST 68
#define VS_ST 72

__global__ __launch_bounds__(128) void attn_mma(const float* __restrict__ qkv,
                                                float* __restrict__ out)
{
    __shared__ uint32_t sK[64 * KS_ST];
    __shared__ uint32_t sV[64 * VS_ST];

    const int tid = threadIdx.x;
    const int lane = tid & 31;
    const int w = tid >> 5;
    const int g = lane >> 2;
    const int t = lane & 3;
    const int bh = blockIdx.y;
    const int b = bh >> 4, h = bh & 15;
    const int q0 = blockIdx.x * 64;

    const size_t row3D = 3 * (size_t)D_;
    const size_t hoff = (size_t)h * HD_;

    // ---- stage Q (scaled by 1/8, tf32) through sK, grab A-frags ----
#pragma unroll
    for (int i = 0; i < 8; i++) {
        int idx = tid + i * 128;
        int r = idx >> 4, c = (idx & 15) << 2;
        float4 v = *(const float4*)(qkv + (size_t)(b * S_ + q0 + r) * row3D + hoff + c);
        uint4 u;
        u.x = f2tf32(v.x * 0.125f); u.y = f2tf32(v.y * 0.125f);
        u.z = f2tf32(v.z * 0.125f); u.w = f2tf32(v.w * 0.125f);
        *(uint4*)&sK[r * KS_ST + c] = u;
    }
    __syncthreads();

    const int r0 = w * 16 + g;
    uint32_t aq[8][4];
#pragma unroll
    for (int j = 0; j < 8; j++) {
        aq[j][0] = sK[r0 * KS_ST + 8 * j + t];
        aq[j][1] = sK[(r0 + 8) * KS_ST + 8 * j + t];
        aq[j][2] = sK[r0 * KS_ST + 8 * j + t + 4];
        aq[j][3] = sK[(r0 + 8) * KS_ST + 8 * j + t + 4];
    }
    __syncthreads();

    float m0 = -3.0e38f, m1 = -3.0e38f, l0 = 0.f, l1 = 0.f;
    float acc_o[8][4];
#pragma unroll
    for (int nt = 0; nt < 8; nt++)
#pragma unroll
        for (int r = 0; r < 4; r++) acc_o[nt][r] = 0.f;

    for (int kv0 = 0; kv0 < S_; kv0 += 64) {
        // ---- fill K, V tiles (tf32) ----
#pragma unroll
        for (int i = 0; i < 8; i++) {
            int idx = tid + i * 128;
            int r = idx >> 4, c = (idx & 15) << 2;
            const float* base = qkv + (size_t)(b * S_ + kv0 + r) * row3D + hoff;
            float4 kk = *(const float4*)(base + D_ + c);
            float4 vv = *(const float4*)(base + 2 * D_ + c);
            uint4 uk, uv;
            uk.x = f2tf32(kk.x); uk.y = f2tf32(kk.y);
            uk.z = f2tf32(kk.z); uk.w = f2tf32(kk.w);
            uv.x = f2tf32(vv.x); uv.y = f2tf32(vv.y);
            uv.z = f2tf32(vv.z); uv.w = f2tf32(vv.w);
            *(uint4*)&sK[r * KS_ST + c] = uk;
            *(uint4*)&sV[r * VS_ST + c] = uv;
        }
        __syncthreads();

        // ---- S = Q @ K^T (tensor) ----
        float acc_s[8][4];
#pragma unroll
        for (int nt = 0; nt < 8; nt++)
#pragma unroll
            for (int r = 0; r < 4; r++) acc_s[nt][r] = 0.f;

#pragma unroll
        for (int j = 0; j < 8; j++) {
#pragma unroll
            for (int nt = 0; nt < 8; nt++) {
                const uint32_t* kb = &sK[(nt * 8 + g) * KS_ST + 8 * j + t];
                mma_tf32(acc_s[nt][0], acc_s[nt][1], acc_s[nt][2], acc_s[nt][3],
                         aq[j][0], aq[j][1], aq[j][2], aq[j][3],
                         kb[0], kb[4]);
            }
        }

        // ---- online softmax ----
        float mx0 = -3.0e38f, mx1 = -3.0e38f;
#pragma unroll
        for (int nt = 0; nt < 8; nt++) {
            mx0 = fmaxf(mx0, fmaxf(acc_s[nt][0], acc_s[nt][1]));
            mx1 = fmaxf(mx1, fmaxf(acc_s[nt][2], acc_s[nt][3]));
        }
        mx0 = fmaxf(mx0, __shfl_xor_sync(0xffffffffu, mx0, 1));
        mx0 = fmaxf(mx0, __shfl_xor_sync(0xffffffffu, mx0, 2));
        mx1 = fmaxf(mx1, __shfl_xor_sync(0xffffffffu, mx1, 1));
        mx1 = fmaxf(mx1, __shfl_xor_sync(0xffffffffu, mx1, 2));

        float mn0 = fmaxf(m0, mx0), mn1 = fmaxf(m1, mx1);
        float al0 = __expf(m0 - mn0), al1 = __expf(m1 - mn1);
        m0 = mn0; m1 = mn1;

        uint32_t ps[8][4];
        float sum0 = 0.f, sum1 = 0.f;
#pragma unroll
        for (int nt = 0; nt < 8; nt++) {
            uint32_t u;
            u = f2tf32(__expf(acc_s[nt][0] - mn0)); ps[nt][0] = u; sum0 += __uint_as_float(u);
            u = f2tf32(__expf(acc_s[nt][1] - mn0)); ps[nt][1] = u; sum0 += __uint_as_float(u);
            u = f2tf32(__expf(acc_s[nt][2] - mn1)); ps[nt][2] = u; sum1 += __uint_as_float(u);
            u = f2tf32(__expf(acc_s[nt][3] - mn1)); ps[nt][3] = u; sum1 += __uint_as_float(u);
        }
        sum0 += __shfl_xor_sync(0xffffffffu, sum0, 1);
        sum0 += __shfl_xor_sync(0xffffffffu, sum0, 2);
        sum1 += __shfl_xor_sync(0xffffffffu, sum1, 1);
        sum1 += __shfl_xor_sync(0xffffffffu, sum1, 2);
        l0 = l0 * al0 + sum0;
        l1 = l1 * al1 + sum1;

#pragma unroll
        for (int nt = 0; nt < 8; nt++) {
            acc_o[nt][0] *= al0; acc_o[nt][1] *= al0;
            acc_o[nt][2] *= al1; acc_o[nt][3] *= al1;
        }

        // ---- O += P @ V (tensor); C-layout -> A-layout via quad shuffles ----
        const int src0 = (lane & ~3) | (t >> 1);
        const int src1 = src0 + 2;
        const bool odd = (t & 1);
#pragma unroll
        for (int j = 0; j < 8; j++) {
            uint32_t q00 = __shfl_sync(0xffffffffu, ps[j][0], src0);
            uint32_t q01 = __shfl_sync(0xffffffffu, ps[j][1], src0);
            uint32_t q20 = __shfl_sync(0xffffffffu, ps[j][2], src0);
            uint32_t q21 = __shfl_sync(0xffffffffu, ps[j][3], src0);
            uint32_t q10 = __shfl_sync(0xffffffffu, ps[j][0], src1);
            uint32_t q11 = __shfl_sync(0xffffffffu, ps[j][1], src1);
            uint32_t q30 = __shfl_sync(0xffffffffu, ps[j][2], src1);
            uint32_t q31 = __shfl_sync(0xffffffffu, ps[j][3], src1);
            uint32_t a0 = odd ? q01 : q00;
            uint32_t a1 = odd ? q21 : q20;
            uint32_t a2 = odd ? q11 : q10;
            uint32_t a3 = odd ? q31 : q30;
#pragma unroll
            for (int nt = 0; nt < 8; nt++) {
                const uint32_t* vb = &sV[(8 * j + t) * VS_ST + nt * 8 + g];
                mma_tf32(acc_o[nt][0], acc_o[nt][1], acc_o[nt][2], acc_o[nt][3],
                         a0, a1, a2, a3,
                         vb[0], vb[4 * VS_ST]);
            }
        }
        __syncthreads();   // done reading sK/sV before next fill
    }

    // ---- epilogue ----
    const float inv0 = 1.f / l0, inv1 = 1.f / l1;
    float* out0 = out + (size_t)(b * S_ + q0 + r0) * D_ + hoff;
    float* out1 = out + (size_t)(b * S_ + q0 + r0 + 8) * D_ + hoff;
#pragma unroll
    for (int nt = 0; nt < 8; nt++) {
        int c = nt * 8 + 2 * t;
        *(float2*)(out0 + c) = make_float2(acc_o[nt][0] * inv0, acc_o[nt][1] * inv0);
        *(float2*)(out1 + c) = make_float2(acc_o[nt][2] * inv1, acc_o[nt][3] * inv1);
    }
}

// ---------------------------------------------------------------------------
extern "C" void kernel_launch(void* const* d_in, const int* in_sizes, int n_in,
                              void* d_out, int out_size)
{
    const float* x      = (const float*)d_in[0];
    const float* w_qkv  = (const float*)d_in[1];
    const float* b_qkv  = (const float*)d_in[2];
    const float* w_proj = (const float*)d_in[3];
    const float* b_proj = (const float*)d_in[4];
    float* out = (float*)d_out;

    float *qkv_ptr, *attn_ptr;
    cudaGetSymbolAddress((void**)&qkv_ptr,  g_qkv);
    cudaGetSymbolAddress((void**)&attn_ptr, g_attn);

    const int smem_bytes = SMEM_FLOATS * 4;  // 71680
    static bool attr_set = false;
    if (!attr_set) {
        cudaFuncSetAttribute(gemm_mma, cudaFuncAttributeMaxDynamicSharedMemorySize,
                             smem_bytes);
        attr_set = true;
    }

    // 1) QKV projection (tf32 mma.sync)
    gemm_mma<<<dim3(3 * D_ / 128, M_ / 128), 256, smem_bytes>>>(
        x, w_qkv, b_qkv, qkv_ptr, 3 * D_, D_);

    // 2) Attention (tf32 mma.sync flash)
    attn_mma<<<dim3(S_ / 64, B_ * H_), 128>>>(qkv_ptr, attn_ptr);

    // 3) Output projection (tf32 mma.sync)
    gemm_mma<<<dim3(D_ / 128, M_ / 128), 256, smem_bytes>>>(
        attn_ptr, w_proj, b_proj, out, D_, D_);
}

// round 5
// speedup vs baseline: 3.7678x; 1.2786x over previous
#include <cuda_runtime.h>
#include <cstdint>
#include <math.h>

#define B_  4
#define S_  2048
#define D_  1024
#define H_  16
#define HD_ 64
#define M_  (B_ * S_)   // 8192

__device__ float g_qkv[(size_t)M_ * 3 * D_];   // [B*S, 3D], tf32-rounded
__device__ float g_attn[(size_t)M_ * D_];      // [B*S, D],  tf32-rounded
__device__ float g_x  [(size_t)M_ * D_];       // rounded x
__device__ float g_wq [(size_t)D_ * 3 * D_];   // rounded w_qkv
__device__ float g_wp [(size_t)D_ * D_];       // rounded w_proj

__device__ __forceinline__ uint32_t f2tf32(float f) {
    uint32_t u;
    asm("cvt.rna.tf32.f32 %0, %1;" : "=r"(u) : "f"(f));
    return u;
}

__device__ __forceinline__ void mma_tf32(float& d0, float& d1, float& d2, float& d3,
                                         uint32_t a0, uint32_t a1, uint32_t a2, uint32_t a3,
                                         uint32_t b0, uint32_t b1) {
    asm volatile(
        "mma.sync.aligned.m16n8k8.row.col.f32.tf32.tf32.f32 "
        "{%0,%1,%2,%3}, {%4,%5,%6,%7}, {%8,%9}, {%0,%1,%2,%3};"
        : "+f"(d0), "+f"(d1), "+f"(d2), "+f"(d3)
        : "r"(a0), "r"(a1), "r"(a2), "r"(a3), "r"(b0), "r"(b1));
}

__device__ __forceinline__ uint32_t smem_u32(const void* p) {
    uint32_t a;
    asm("{ .reg .u64 t; cvta.to.shared.u64 t, %1; cvt.u32.u64 %0, t; }"
        : "=r"(a) : "l"(p));
    return a;
}

__device__ __forceinline__ void cp16(uint32_t dst, const void* src) {
    asm volatile("cp.async.cg.shared.global [%0], [%1], 16;"
                 :: "r"(dst), "l"(src) : "memory");
}
__device__ __forceinline__ void cp_commit() {
    asm volatile("cp.async.commit_group;" ::: "memory");
}
__device__ __forceinline__ void cp_wait1() {
    asm volatile("cp.async.wait_group 1;" ::: "memory");
}
__device__ __forceinline__ void cp_wait0() {
    asm volatile("cp.async.wait_group 0;" ::: "memory");
}

// ---------------------------------------------------------------------------
// Pre-pass: tf32-round an array (float4 granularity; sizes are multiples of 4)
// ---------------------------------------------------------------------------
__global__ void round_tf32(const float4* __restrict__ src, float4* __restrict__ dst,
                           int n4)
{
    int i = blockIdx.x * blockDim.x + threadIdx.x;
    if (i < n4) {
        float4 v = src[i];
        uint4 u;
        u.x = f2tf32(v.x); u.y = f2tf32(v.y);
        u.z = f2tf32(v.z); u.w = f2tf32(v.w);
        *(uint4*)&dst[i] = u;
    }
}

// ---------------------------------------------------------------------------
// TF32 mma.sync GEMM + bias, cp.async 3-stage pipeline.
// Inputs A, W must be tf32-rounded already. round_out: round C to tf32.
// CTA 128x128, BK=32, 256 threads, warp tile 64x32.
// ---------------------------------------------------------------------------
#define AS_STRIDE 36
#define BS_STRIDE 136
#define AS_TILE   (128 * AS_STRIDE)
#define BS_TILE   (32 * BS_STRIDE)
#define GEMM_SMEM (3 * (AS_TILE + BS_TILE) * 4)   // 107520 B

__global__ __launch_bounds__(256) void gemm_mma(
    const float* __restrict__ A, const float* __restrict__ W,
    const float* __restrict__ bias, float* __restrict__ C,
    int N, int K, int round_out)
{
    extern __shared__ __align__(16) float sm[];
    const uint32_t sAaddr = smem_u32(sm);
    const uint32_t sBaddr = sAaddr + 3u * AS_TILE * 4u;

    const int tid = threadIdx.x;
    const int lane = tid & 31, wid = tid >> 5;
    const int wm = wid & 1, wn = wid >> 1;
    const int bx = blockIdx.x, by = blockIdx.y;
    const int g = lane >> 2, t = lane & 3;

    const int arow = tid >> 3;            // 0..31
    const int acol = (tid & 7) << 2;      // 0..28
    const int brow = tid >> 5;            // 0..7
    const int bcol = (tid & 31) << 2;     // 0..124
    const float* Ag = A + (size_t)(by * 128 + arow) * K + acol;
    const float* Wg = W + (size_t)brow * N + bx * 128 + bcol;

    uint32_t aoff[4], boff[4];
#pragma unroll
    for (int i = 0; i < 4; i++) {
        aoff[i] = (uint32_t)(((arow + i * 32) * AS_STRIDE + acol) * 4);
        boff[i] = (uint32_t)(((brow + i * 8) * BS_STRIDE + bcol) * 4);
    }

    const int nstages = K >> 5;

    // --- issue helper (inlined) ---
    auto issue = [&](int s, int buf) {
        const uint32_t dA = sAaddr + (uint32_t)buf * (AS_TILE * 4u);
        const uint32_t dB = sBaddr + (uint32_t)buf * (BS_TILE * 4u);
        const float* a_ = Ag + (s << 5);
        const float* w_ = Wg + (size_t)(s << 5) * N;
#pragma unroll
        for (int i = 0; i < 4; i++) {
            cp16(dA + aoff[i], a_ + (size_t)i * 32 * K);
            cp16(dB + boff[i], w_ + (size_t)i * 8 * N);
        }
        cp_commit();
    };

    issue(0, 0);
    issue(1, 1);

    float acc[4][4][4];
#pragma unroll
    for (int mt = 0; mt < 4; mt++)
#pragma unroll
        for (int nt = 0; nt < 4; nt++)
#pragma unroll
            for (int r = 0; r < 4; r++) acc[mt][nt][r] = 0.f;

    cp_wait1();          // stage 0 ready
    __syncthreads();

    const uint32_t* smu = (const uint32_t*)sm;

    for (int s = 0; s < nstages; s++) {
        const int buf = s % 3;
        const uint32_t* cA = smu + buf * AS_TILE;
        const uint32_t* cB = smu + 3 * AS_TILE + buf * BS_TILE;

#pragma unroll
        for (int ks = 0; ks < 4; ks++) {
            const int k0 = ks << 3;
            uint32_t af[4][4], bf[4][2];
#pragma unroll
            for (int mt = 0; mt < 4; mt++) {
                const uint32_t* base = cA + (wm * 64 + mt * 16 + g) * AS_STRIDE + k0 + t;
                af[mt][0] = base[0];
                af[mt][1] = base[8 * AS_STRIDE];
                af[mt][2] = base[4];
                af[mt][3] = base[8 * AS_STRIDE + 4];
            }
#pragma unroll
            for (int nt = 0; nt < 4; nt++) {
                const uint32_t* base = cB + (k0 + t) * BS_STRIDE + wn * 32 + nt * 8 + g;
                bf[nt][0] = base[0];
                bf[nt][1] = base[4 * BS_STRIDE];
            }
#pragma unroll
            for (int mt = 0; mt < 4; mt++)
#pragma unroll
                for (int nt = 0; nt < 4; nt++)
                    mma_tf32(acc[mt][nt][0], acc[mt][nt][1], acc[mt][nt][2], acc[mt][nt][3],
                             af[mt][0], af[mt][1], af[mt][2], af[mt][3],
                             bf[nt][0], bf[nt][1]);
        }

        if (s + 2 < nstages) {
            issue(s + 2, (s + 2) % 3);
            cp_wait1();       // stage s+1 ready
        } else {
            cp_wait0();
        }
        __syncthreads();
    }

    // ---- epilogue ----
#pragma unroll
    for (int nt = 0; nt < 4; nt++) {
        const int c = bx * 128 + wn * 32 + nt * 8 + 2 * t;
        const float bx0 = bias[c], bx1 = bias[c + 1];
#pragma unroll
        for (int mt = 0; mt < 4; mt++) {
            const int r0 = by * 128 + wm * 64 + mt * 16 + g;
            float v00 = acc[mt][nt][0] + bx0, v01 = acc[mt][nt][1] + bx1;
            float v10 = acc[mt][nt][2] + bx0, v11 = acc[mt][nt][3] + bx1;
            if (round_out) {
                v00 = __uint_as_float(f2tf32(v00));
                v01 = __uint_as_float(f2tf32(v01));
                v10 = __uint_as_float(f2tf32(v10));
                v11 = __uint_as_float(f2tf32(v11));
            }
            *(float2*)(C + (size_t)r0 * N + c)       = make_float2(v00, v01);
            *(float2*)(C + (size_t)(r0 + 8) * N + c) = make_float2(v10, v11);
        }
    }
}

// ---------------------------------------------------------------------------
// TF32 mma.sync flash attention, cp.async double-buffered K/V.
// qkv values are already tf32-rounded. Block = 128 threads = 64 q-rows.
// ---------------------------------------------------------------------------
#define KS_ST 68
#define VS_ST 72
#define ATTN_SMEM ((2 * 64 * KS_ST + 2 * 64 * VS_ST) * 4)   // 71680 B

__global__ __launch_bounds__(128) void attn_mma(const float* __restrict__ qkv,
                                                float* __restrict__ out)
{
    extern __shared__ __align__(16) uint32_t smu[];
    uint32_t* sKu = smu;                       // [2][64*KS_ST]
    uint32_t* sVu = smu + 2 * 64 * KS_ST;      // [2][64*VS_ST]
    const uint32_t sKaddr = smem_u32(sKu);
    const uint32_t sVaddr = smem_u32(sVu);

    const int tid = threadIdx.x;
    const int lane = tid & 31;
    const int w = tid >> 5;
    const int g = lane >> 2;
    const int t = lane & 3;
    const int bh = blockIdx.y;
    const int b = bh >> 4, h = bh & 15;
    const int q0 = blockIdx.x * 64;

    const size_t row3D = 3 * (size_t)D_;
    const size_t hoff = (size_t)h * HD_;

    const int krow = tid >> 4;            // 0..7
    const int kcol = (tid & 15) << 2;     // 0..60

    // ---- stage Q (scaled by 1/8; values already tf32 so scale is exact) ----
#pragma unroll
    for (int i = 0; i < 8; i++) {
        int idx = tid + i * 128;
        int r = idx >> 4, c = (idx & 15) << 2;
        float4 v = *(const float4*)(qkv + (size_t)(b * S_ + q0 + r) * row3D + hoff + c);
        uint4 u;
        u.x = __float_as_uint(v.x * 0.125f); u.y = __float_as_uint(v.y * 0.125f);
        u.z = __float_as_uint(v.z * 0.125f); u.w = __float_as_uint(v.w * 0.125f);
        *(uint4*)&sKu[r * KS_ST + c] = u;
    }
    __syncthreads();

    const int r0 = w * 16 + g;
    uint32_t aq[8][4];
#pragma unroll
    for (int j = 0; j < 8; j++) {
        aq[j][0] = sKu[r0 * KS_ST + 8 * j + t];
        aq[j][1] = sKu[(r0 + 8) * KS_ST + 8 * j + t];
        aq[j][2] = sKu[r0 * KS_ST + 8 * j + t + 4];
        aq[j][3] = sKu[(r0 + 8) * KS_ST + 8 * j + t + 4];
    }
    __syncthreads();

    // ---- fill helper ----
    const float* kvbase = qkv + (size_t)(b * S_ + krow) * row3D + hoff + kcol;
    auto issue = [&](int tile, int buf) {
        const float* src = kvbase + (size_t)tile * 64 * row3D;
        const uint32_t dK = sKaddr + (uint32_t)buf * (64 * KS_ST * 4u);
        const uint32_t dV = sVaddr + (uint32_t)buf * (64 * VS_ST * 4u);
#pragma unroll
        for (int i = 0; i < 8; i++) {
            cp16(dK + (uint32_t)(((krow + i * 8) * KS_ST + kcol) * 4),
                 src + (size_t)i * 8 * row3D + D_);
            cp16(dV + (uint32_t)(((krow + i * 8) * VS_ST + kcol) * 4),
                 src + (size_t)i * 8 * row3D + 2 * D_);
        }
        cp_commit();
    };

    issue(0, 0);

    float m0 = -3.0e38f, m1 = -3.0e38f, l0 = 0.f, l1 = 0.f;
    float acc_o[8][4];
#pragma unroll
    for (int nt = 0; nt < 8; nt++)
#pragma unroll
        for (int r = 0; r < 4; r++) acc_o[nt][r] = 0.f;

    const int ntiles = S_ / 64;   // 32
    for (int i = 0; i < ntiles; i++) {
        const int buf = i & 1;
        if (i + 1 < ntiles) {
            issue(i + 1, buf ^ 1);
            cp_wait1();           // tile i ready
        } else {
            cp_wait0();
        }
        __syncthreads();

        const uint32_t* cK = sKu + buf * (64 * KS_ST);
        const uint32_t* cV = sVu + buf * (64 * VS_ST);

        // ---- S = Q @ K^T ----
        float acc_s[8][4];
#pragma unroll
        for (int nt = 0; nt < 8; nt++)
#pragma unroll
            for (int r = 0; r < 4; r++) acc_s[nt][r] = 0.f;

#pragma unroll
        for (int j = 0; j < 8; j++) {
#pragma unroll
            for (int nt = 0; nt < 8; nt++) {
                const uint32_t* kb = &cK[(nt * 8 + g) * KS_ST + 8 * j + t];
                mma_tf32(acc_s[nt][0], acc_s[nt][1], acc_s[nt][2], acc_s[nt][3],
                         aq[j][0], aq[j][1], aq[j][2], aq[j][3],
                         kb[0], kb[4]);
            }
        }

        // ---- online softmax ----
        float mx0 = -3.0e38f, mx1 = -3.0e38f;
#pragma unroll
        for (int nt = 0; nt < 8; nt++) {
            mx0 = fmaxf(mx0, fmaxf(acc_s[nt][0], acc_s[nt][1]));
            mx1 = fmaxf(mx1, fmaxf(acc_s[nt][2], acc_s[nt][3]));
        }
        mx0 = fmaxf(mx0, __shfl_xor_sync(0xffffffffu, mx0, 1));
        mx0 = fmaxf(mx0, __shfl_xor_sync(0xffffffffu, mx0, 2));
        mx1 = fmaxf(mx1, __shfl_xor_sync(0xffffffffu, mx1, 1));
        mx1 = fmaxf(mx1, __shfl_xor_sync(0xffffffffu, mx1, 2));

        float mn0 = fmaxf(m0, mx0), mn1 = fmaxf(m1, mx1);
        float al0 = __expf(m0 - mn0), al1 = __expf(m1 - mn1);
        m0 = mn0; m1 = mn1;

        uint32_t ps[8][4];
        float sum0 = 0.f, sum1 = 0.f;
#pragma unroll
        for (int nt = 0; nt < 8; nt++) {
            uint32_t u;
            u = f2tf32(__expf(acc_s[nt][0] - mn0)); ps[nt][0] = u; sum0 += __uint_as_float(u);
            u = f2tf32(__expf(acc_s[nt][1] - mn0)); ps[nt][1] = u; sum0 += __uint_as_float(u);
            u = f2tf32(__expf(acc_s[nt][2] - mn1)); ps[nt][2] = u; sum1 += __uint_as_float(u);
            u = f2tf32(__expf(acc_s[nt][3] - mn1)); ps[nt][3] = u; sum1 += __uint_as_float(u);
        }
        sum0 += __shfl_xor_sync(0xffffffffu, sum0, 1);
        sum0 += __shfl_xor_sync(0xffffffffu, sum0, 2);
        sum1 += __shfl_xor_sync(0xffffffffu, sum1, 1);
        sum1 += __shfl_xor_sync(0xffffffffu, sum1, 2);
        l0 = l0 * al0 + sum0;
        l1 = l1 * al1 + sum1;

#pragma unroll
        for (int nt = 0; nt < 8; nt++) {
            acc_o[nt][0] *= al0; acc_o[nt][1] *= al0;
            acc_o[nt][2] *= al1; acc_o[nt][3] *= al1;
        }

        // ---- O += P @ V ----
        const int src0 = (lane & ~3) | (t >> 1);
        const int src1 = src0 + 2;
        const bool odd = (t & 1);
#pragma unroll
        for (int j = 0; j < 8; j++) {
            uint32_t q00 = __shfl_sync(0xffffffffu, ps[j][0], src0);
            uint32_t q01 = __shfl_sync(0xffffffffu, ps[j][1], src0);
            uint32_t q20 = __shfl_sync(0xffffffffu, ps[j][2], src0);
            uint32_t q21 = __shfl_sync(0xffffffffu, ps[j][3], src0);
            uint32_t q10 = __shfl_sync(0xffffffffu, ps[j][0], src1);
            uint32_t q11 = __shfl_sync(0xffffffffu, ps[j][1], src1);
            uint32_t q30 = __shfl_sync(0xffffffffu, ps[j][2], src1);
            uint32_t q31 = __shfl_sync(0xffffffffu, ps[j][3], src1);
            uint32_t a0 = odd ? q01 : q00;
            uint32_t a1 = odd ? q21 : q20;
            uint32_t a2 = odd ? q11 : q10;
            uint32_t a3 = odd ? q31 : q30;
#pragma unroll
            for (int nt = 0; nt < 8; nt++) {
                const uint32_t* vb = &cV[(8 * j + t) * VS_ST + nt * 8 + g];
                mma_tf32(acc_o[nt][0], acc_o[nt][1], acc_o[nt][2], acc_o[nt][3],
                         a0, a1, a2, a3,
                         vb[0], vb[4 * VS_ST]);
            }
        }
        __syncthreads();   // all reads of buf done before it is refilled
    }

    // ---- epilogue (tf32-rounded so proj GEMM consumes directly) ----
    const float inv0 = 1.f / l0, inv1 = 1.f / l1;
    float* out0 = out + (size_t)(b * S_ + q0 + r0) * D_ + hoff;
    float* out1 = out + (size_t)(b * S_ + q0 + r0 + 8) * D_ + hoff;
#pragma unroll
    for (int nt = 0; nt < 8; nt++) {
        int c = nt * 8 + 2 * t;
        float2 v0, v1;
        v0.x = __uint_as_float(f2tf32(acc_o[nt][0] * inv0));
        v0.y = __uint_as_float(f2tf32(acc_o[nt][1] * inv0));
        v1.x = __uint_as_float(f2tf32(acc_o[nt][2] * inv1));
        v1.y = __uint_as_float(f2tf32(acc_o[nt][3] * inv1));
        *(float2*)(out0 + c) = v0;
        *(float2*)(out1 + c) = v1;
    }
}

// ---------------------------------------------------------------------------
extern "C" void kernel_launch(void* const* d_in, const int* in_sizes, int n_in,
                              void* d_out, int out_size)
{
    const float* x      = (const float*)d_in[0];
    const float* w_qkv  = (const float*)d_in[1];
    const float* b_qkv  = (const float*)d_in[2];
    const float* w_proj = (const float*)d_in[3];
    const float* b_proj = (const float*)d_in[4];
    float* out = (float*)d_out;

    float *qkv_p, *attn_p, *x_p, *wq_p, *wp_p;
    cudaGetSymbolAddress((void**)&qkv_p,  g_qkv);
    cudaGetSymbolAddress((void**)&attn_p, g_attn);
    cudaGetSymbolAddress((void**)&x_p,    g_x);
    cudaGetSymbolAddress((void**)&wq_p,   g_wq);
    cudaGetSymbolAddress((void**)&wp_p,   g_wp);

    static bool attr_set = false;
    if (!attr_set) {
        cudaFuncSetAttribute(gemm_mma, cudaFuncAttributeMaxDynamicSharedMemorySize,
                             GEMM_SMEM);
        cudaFuncSetAttribute(attn_mma, cudaFuncAttributeMaxDynamicSharedMemorySize,
                             ATTN_SMEM);
        attr_set = true;
    }

    // 0) tf32 pre-rounding of inputs
    const int n4x = M_ * D_ / 4;          // 2097152
    const int n4q = D_ * 3 * D_ / 4;      // 786432
    const int n4p = D_ * D_ / 4;          // 262144
    round_tf32<<<(n4x + 255) / 256, 256>>>((const float4*)x,      (float4*)x_p,  n4x);
    round_tf32<<<(n4q + 255) / 256, 256>>>((const float4*)w_qkv,  (float4*)wq_p, n4q);
    round_tf32<<<(n4p + 255) / 256, 256>>>((const float4*)w_proj, (float4*)wp_p, n4p);

    // 1) QKV projection (rounded output feeds attention)
    gemm_mma<<<dim3(3 * D_ / 128, M_ / 128), 256, GEMM_SMEM>>>(
        x_p, wq_p, b_qkv, qkv_p, 3 * D_, D_, 1);

    // 2) Attention (rounded output feeds proj GEMM)
    attn_mma<<<dim3(S_ / 64, B_ * H_), 128, ATTN_SMEM>>>(qkv_p, attn_p);

    // 3) Output projection (full fp32 output)
    gemm_mma<<<dim3(D_ / 128, M_ / 128), 256, GEMM_SMEM>>>(
        attn_p, wp_p, b_proj, out, D_, D_, 0);
}

// round 6
// speedup vs baseline: 4.2965x; 1.1403x over previous
#include <cuda_runtime.h>
#include <cstdint>
#include <math.h>

#define B_  4
#define S_  2048
#define D_  1024
#define H_  16
#define HD_ 64
#define M_  (B_ * S_)   // 8192

__device__ float g_qkv[(size_t)M_ * 3 * D_];   // [B*S, 3D], tf32-rounded
__device__ float g_attn[(size_t)M_ * D_];      // [B*S, D],  tf32-rounded
__device__ float g_x  [(size_t)M_ * D_];       // rounded x
__device__ float g_wq [(size_t)D_ * 3 * D_];   // rounded w_qkv
__device__ float g_wp [(size_t)D_ * D_];       // rounded w_proj

__device__ __forceinline__ uint32_t f2tf32(float f) {
    uint32_t u;
    asm("cvt.rna.tf32.f32 %0, %1;" : "=r"(u) : "f"(f));
    return u;
}

__device__ __forceinline__ void mma_tf32(float& d0, float& d1, float& d2, float& d3,
                                         uint32_t a0, uint32_t a1, uint32_t a2, uint32_t a3,
                                         uint32_t b0, uint32_t b1) {
    asm volatile(
        "mma.sync.aligned.m16n8k8.row.col.f32.tf32.tf32.f32 "
        "{%0,%1,%2,%3}, {%4,%5,%6,%7}, {%8,%9}, {%0,%1,%2,%3};"
        : "+f"(d0), "+f"(d1), "+f"(d2), "+f"(d3)
        : "r"(a0), "r"(a1), "r"(a2), "r"(a3), "r"(b0), "r"(b1));
}

__device__ __forceinline__ uint32_t smem_u32(const void* p) {
    uint32_t a;
    asm("{ .reg .u64 t; cvta.to.shared.u64 t, %1; cvt.u32.u64 %0, t; }"
        : "=r"(a) : "l"(p));
    return a;
}

__device__ __forceinline__ void ldsm_x4(uint32_t& r0, uint32_t& r1,
                                        uint32_t& r2, uint32_t& r3, uint32_t addr) {
    asm volatile("ldmatrix.sync.aligned.m8n8.x4.shared.b16 {%0,%1,%2,%3}, [%4];"
                 : "=r"(r0), "=r"(r1), "=r"(r2), "=r"(r3) : "r"(addr));
}
__device__ __forceinline__ void ldsm_x2(uint32_t& r0, uint32_t& r1, uint32_t addr) {
    asm volatile("ldmatrix.sync.aligned.m8n8.x2.shared.b16 {%0,%1}, [%2];"
                 : "=r"(r0), "=r"(r1) : "r"(addr));
}

__device__ __forceinline__ void cp16(uint32_t dst, const void* src) {
    asm volatile("cp.async.cg.shared.global [%0], [%1], 16;"
                 :: "r"(dst), "l"(src) : "memory");
}
__device__ __forceinline__ void cp_commit() {
    asm volatile("cp.async.commit_group;" ::: "memory");
}
__device__ __forceinline__ void cp_wait1() {
    asm volatile("cp.async.wait_group 1;" ::: "memory");
}
__device__ __forceinline__ void cp_wait0() {
    asm volatile("cp.async.wait_group 0;" ::: "memory");
}

// ---------------------------------------------------------------------------
__global__ void round_tf32(const float4* __restrict__ src, float4* __restrict__ dst,
                           int n4)
{
    int i = blockIdx.x * blockDim.x + threadIdx.x;
    if (i < n4) {
        float4 v = src[i];
        uint4 u;
        u.x = f2tf32(v.x); u.y = f2tf32(v.y);
        u.z = f2tf32(v.z); u.w = f2tf32(v.w);
        *(uint4*)&dst[i] = u;
    }
}

// ---------------------------------------------------------------------------
// TF32 mma.sync GEMM + bias, cp.async 3-stage pipeline, ldmatrix A-frags.
// ---------------------------------------------------------------------------
#define AS_STRIDE 36
#define BS_STRIDE 136
#define AS_TILE   (128 * AS_STRIDE)
#define BS_TILE   (32 * BS_STRIDE)
#define GEMM_SMEM (3 * (AS_TILE + BS_TILE) * 4)   // 107520 B

__global__ __launch_bounds__(256) void gemm_mma(
    const float* __restrict__ A, const float* __restrict__ W,
    const float* __restrict__ bias, float* __restrict__ C,
    int N, int K, int round_out)
{
    extern __shared__ __align__(16) float sm[];
    const uint32_t sAaddr = smem_u32(sm);
    const uint32_t sBaddr = sAaddr + 3u * AS_TILE * 4u;

    const int tid = threadIdx.x;
    const int lane = tid & 31, wid = tid >> 5;
    const int wm = wid & 1, wn = wid >> 1;
    const int bx = blockIdx.x, by = blockIdx.y;
    const int g = lane >> 2, t = lane & 3;

    const int arow = tid >> 3;
    const int acol = (tid & 7) << 2;
    const int brow = tid >> 5;
    const int bcol = (tid & 31) << 2;
    const float* Ag = A + (size_t)(by * 128 + arow) * K + acol;
    const float* Wg = W + (size_t)brow * N + bx * 128 + bcol;

    uint32_t aoff[4], boff[4];
#pragma unroll
    for (int i = 0; i < 4; i++) {
        aoff[i] = (uint32_t)(((arow + i * 32) * AS_STRIDE + acol) * 4);
        boff[i] = (uint32_t)(((brow + i * 8) * BS_STRIDE + bcol) * 4);
    }

    // ldmatrix x4 address: row = warp M base + mt*16 + (lane&15), col half by lane>>4
    uint32_t a_lm[4];
#pragma unroll
    for (int mt = 0; mt < 4; mt++)
        a_lm[mt] = (uint32_t)(((wm * 64 + mt * 16 + (lane & 15)) * AS_STRIDE
                               + (lane >> 4) * 4) * 4);

    const int nstages = K >> 5;

    auto issue = [&](int s, int buf) {
        const uint32_t dA = sAaddr + (uint32_t)buf * (AS_TILE * 4u);
        const uint32_t dB = sBaddr + (uint32_t)buf * (BS_TILE * 4u);
        const float* a_ = Ag + (s << 5);
        const float* w_ = Wg + (size_t)(s << 5) * N;
#pragma unroll
        for (int i = 0; i < 4; i++) {
            cp16(dA + aoff[i], a_ + (size_t)i * 32 * K);
            cp16(dB + boff[i], w_ + (size_t)i * 8 * N);
        }
        cp_commit();
    };

    issue(0, 0);
    issue(1, 1);

    float acc[4][4][4];
#pragma unroll
    for (int mt = 0; mt < 4; mt++)
#pragma unroll
        for (int nt = 0; nt < 4; nt++)
#pragma unroll
            for (int r = 0; r < 4; r++) acc[mt][nt][r] = 0.f;

    cp_wait1();
    __syncthreads();

    const uint32_t* smu = (const uint32_t*)sm;

    for (int s = 0; s < nstages; s++) {
        const int buf = s % 3;
        const uint32_t cAaddr = sAaddr + (uint32_t)buf * (AS_TILE * 4u);
        const uint32_t* cB = smu + 3 * AS_TILE + buf * BS_TILE;

#pragma unroll
        for (int ks = 0; ks < 4; ks++) {
            const int k0 = ks << 3;
            uint32_t af[4][4], bf[4][2];
#pragma unroll
            for (int mt = 0; mt < 4; mt++)
                ldsm_x4(af[mt][0], af[mt][1], af[mt][2], af[mt][3],
                        cAaddr + a_lm[mt] + (uint32_t)(k0 * 4));
#pragma unroll
            for (int nt = 0; nt < 4; nt++) {
                const uint32_t* base = cB + (k0 + t) * BS_STRIDE + wn * 32 + nt * 8 + g;
                bf[nt][0] = base[0];
                bf[nt][1] = base[4 * BS_STRIDE];
            }
#pragma unroll
            for (int mt = 0; mt < 4; mt++)
#pragma unroll
                for (int nt = 0; nt < 4; nt++)
                    mma_tf32(acc[mt][nt][0], acc[mt][nt][1], acc[mt][nt][2], acc[mt][nt][3],
                             af[mt][0], af[mt][1], af[mt][2], af[mt][3],
                             bf[nt][0], bf[nt][1]);
        }

        if (s + 2 < nstages) {
            issue(s + 2, (s + 2) % 3);
            cp_wait1();
        } else {
            cp_wait0();
        }
        __syncthreads();
    }

#pragma unroll
    for (int nt = 0; nt < 4; nt++) {
        const int c = bx * 128 + wn * 32 + nt * 8 + 2 * t;
        const float bx0 = bias[c], bx1 = bias[c + 1];
#pragma unroll
        for (int mt = 0; mt < 4; mt++) {
            const int r0 = by * 128 + wm * 64 + mt * 16 + g;
            float v00 = acc[mt][nt][0] + bx0, v01 = acc[mt][nt][1] + bx1;
            float v10 = acc[mt][nt][2] + bx0, v11 = acc[mt][nt][3] + bx1;
            if (round_out) {
                v00 = __uint_as_float(f2tf32(v00));
                v01 = __uint_as_float(f2tf32(v01));
                v10 = __uint_as_float(f2tf32(v10));
                v11 = __uint_as_float(f2tf32(v11));
            }
            *(float2*)(C + (size_t)r0 * N + c)       = make_float2(v00, v01);
            *(float2*)(C + (size_t)(r0 + 8) * N + c) = make_float2(v10, v11);
        }
    }
}

// ---------------------------------------------------------------------------
// TF32 mma.sync flash attention: ldmatrix K-frags, shuffle-free PV via
// per-8-group KV column permutation (V rows stored permuted: r -> r/2 (even),
// (r+7)/2 (odd)), so PV A-frags are the QK C registers reordered (c0,c2,c1,c3).
// ---------------------------------------------------------------------------
#define KS_ST 68
#define VS_ST 72
#define ATTN_SMEM ((2 * 64 * KS_ST + 2 * 64 * VS_ST) * 4)   // 71680 B

__global__ __launch_bounds__(128) void attn_mma(const float* __restrict__ qkv,
                                                float* __restrict__ out)
{
    extern __shared__ __align__(16) uint32_t smu[];
    uint32_t* sKu = smu;
    uint32_t* sVu = smu + 2 * 64 * KS_ST;
    const uint32_t sKaddr = smem_u32(sKu);
    const uint32_t sVaddr = smem_u32(sVu);

    const int tid = threadIdx.x;
    const int lane = tid & 31;
    const int w = tid >> 5;
    const int g = lane >> 2;
    const int t = lane & 3;
    const int bh = blockIdx.y;
    const int b = bh >> 4, h = bh & 15;
    const int q0 = blockIdx.x * 64;

    const size_t row3D = 3 * (size_t)D_;
    const size_t hoff = (size_t)h * HD_;

    const int krow = tid >> 4;            // 0..7
    const int kcol = (tid & 15) << 2;     // 0..60
    const int vperm = (krow & 1) ? (krow >> 1) + 4 : (krow >> 1);

    // ldmatrix x2 per-thread offset for K B-frags
    const int l15 = lane & 15;
    const uint32_t k_lm = (uint32_t)((((l15 & 7) * KS_ST) + ((l15 >> 3) * 4)) * 4);

    // ---- stage Q (scaled by 1/8; exact: values already tf32) ----
#pragma unroll
    for (int i = 0; i < 8; i++) {
        int idx = tid + i * 128;
        int r = idx >> 4, c = (idx & 15) << 2;
        float4 v = *(const float4*)(qkv + (size_t)(b * S_ + q0 + r) * row3D + hoff + c);
        uint4 u;
        u.x = __float_as_uint(v.x * 0.125f); u.y = __float_as_uint(v.y * 0.125f);
        u.z = __float_as_uint(v.z * 0.125f); u.w = __float_as_uint(v.w * 0.125f);
        *(uint4*)&sKu[r * KS_ST + c] = u;
    }
    __syncthreads();

    const int r0 = w * 16 + g;
    uint32_t aq[8][4];
#pragma unroll
    for (int j = 0; j < 8; j++) {
        aq[j][0] = sKu[r0 * KS_ST + 8 * j + t];
        aq[j][1] = sKu[(r0 + 8) * KS_ST + 8 * j + t];
        aq[j][2] = sKu[r0 * KS_ST + 8 * j + t + 4];
        aq[j][3] = sKu[(r0 + 8) * KS_ST + 8 * j + t + 4];
    }
    __syncthreads();

    const float* kvbase = qkv + (size_t)(b * S_ + krow) * row3D + hoff + kcol;
    auto issue = [&](int tile, int buf) {
        const float* src = kvbase + (size_t)tile * 64 * row3D;
        const uint32_t dK = sKaddr + (uint32_t)buf * (64 * KS_ST * 4u);
        const uint32_t dV = sVaddr + (uint32_t)buf * (64 * VS_ST * 4u);
#pragma unroll
        for (int i = 0; i < 8; i++) {
            cp16(dK + (uint32_t)(((krow + i * 8) * KS_ST + kcol) * 4),
                 src + (size_t)i * 8 * row3D + D_);
            cp16(dV + (uint32_t)(((vperm + i * 8) * VS_ST + kcol) * 4),
                 src + (size_t)i * 8 * row3D + 2 * D_);
        }
        cp_commit();
    };

    issue(0, 0);

    float m0 = -3.0e38f, m1 = -3.0e38f, l0 = 0.f, l1 = 0.f;
    float acc_o[8][4];
#pragma unroll
    for (int nt = 0; nt < 8; nt++)
#pragma unroll
        for (int r = 0; r < 4; r++) acc_o[nt][r] = 0.f;

    const int ntiles = S_ / 64;
    for (int i = 0; i < ntiles; i++) {
        const int buf = i & 1;
        if (i + 1 < ntiles) {
            issue(i + 1, buf ^ 1);
            cp_wait1();
        } else {
            cp_wait0();
        }
        __syncthreads();

        const uint32_t cKaddr = sKaddr + (uint32_t)buf * (64 * KS_ST * 4u);
        const uint32_t* cV = sVu + buf * (64 * VS_ST);

        // ---- S = Q @ K^T (ldmatrix B-frags) ----
        float acc_s[8][4];
#pragma unroll
        for (int nt = 0; nt < 8; nt++)
#pragma unroll
            for (int r = 0; r < 4; r++) acc_s[nt][r] = 0.f;

#pragma unroll
        for (int j = 0; j < 8; j++) {
#pragma unroll
            for (int nt = 0; nt < 8; nt++) {
                uint32_t b0, b1;
                ldsm_x2(b0, b1,
                        cKaddr + k_lm + (uint32_t)(((nt * 8) * KS_ST + 8 * j) * 4));
                mma_tf32(acc_s[nt][0], acc_s[nt][1], acc_s[nt][2], acc_s[nt][3],
                         aq[j][0], aq[j][1], aq[j][2], aq[j][3],
                         b0, b1);
            }
        }

        // ---- online softmax ----
        float mx0 = -3.0e38f, mx1 = -3.0e38f;
#pragma unroll
        for (int nt = 0; nt < 8; nt++) {
            mx0 = fmaxf(mx0, fmaxf(acc_s[nt][0], acc_s[nt][1]));
            mx1 = fmaxf(mx1, fmaxf(acc_s[nt][2], acc_s[nt][3]));
        }
        mx0 = fmaxf(mx0, __shfl_xor_sync(0xffffffffu, mx0, 1));
        mx0 = fmaxf(mx0, __shfl_xor_sync(0xffffffffu, mx0, 2));
        mx1 = fmaxf(mx1, __shfl_xor_sync(0xffffffffu, mx1, 1));
        mx1 = fmaxf(mx1, __shfl_xor_sync(0xffffffffu, mx1, 2));

        float mn0 = fmaxf(m0, mx0), mn1 = fmaxf(m1, mx1);
        float al0 = __expf(m0 - mn0), al1 = __expf(m1 - mn1);
        m0 = mn0; m1 = mn1;

        uint32_t ps[8][4];
        float sum0 = 0.f, sum1 = 0.f;
#pragma unroll
        for (int nt = 0; nt < 8; nt++) {
            uint32_t u;
            u = f2tf32(__expf(acc_s[nt][0] - mn0)); ps[nt][0] = u; sum0 += __uint_as_float(u);
            u = f2tf32(__expf(acc_s[nt][1] - mn0)); ps[nt][1] = u; sum0 += __uint_as_float(u);
            u = f2tf32(__expf(acc_s[nt][2] - mn1)); ps[nt][2] = u; sum1 += __uint_as_float(u);
            u = f2tf32(__expf(acc_s[nt][3] - mn1)); ps[nt][3] = u; sum1 += __uint_as_float(u);
        }
        sum0 += __shfl_xor_sync(0xffffffffu, sum0, 1);
        sum0 += __shfl_xor_sync(0xffffffffu, sum0, 2);
        sum1 += __shfl_xor_sync(0xffffffffu, sum1, 1);
        sum1 += __shfl_xor_sync(0xffffffffu, sum1, 2);
        l0 = l0 * al0 + sum0;
        l1 = l1 * al1 + sum1;

#pragma unroll
        for (int nt = 0; nt < 8; nt++) {
            acc_o[nt][0] *= al0; acc_o[nt][1] *= al0;
            acc_o[nt][2] *= al1; acc_o[nt][3] *= al1;
        }

        // ---- O += P @ V (shuffle-free: V rows permuted, A = (c0,c2,c1,c3)) ----
#pragma unroll
        for (int j = 0; j < 8; j++) {
            const uint32_t a0 = ps[j][0], a1 = ps[j][2];
            const uint32_t a2 = ps[j][1], a3 = ps[j][3];
#pragma unroll
            for (int nt = 0; nt < 8; nt++) {
                const uint32_t* vb = &cV[(8 * j + t) * VS_ST + nt * 8 + g];
                mma_tf32(acc_o[nt][0], acc_o[nt][1], acc_o[nt][2], acc_o[nt][3],
                         a0, a1, a2, a3,
                         vb[0], vb[4 * VS_ST]);
            }
        }
        __syncthreads();
    }

    // ---- epilogue (tf32-rounded for proj GEMM) ----
    const float inv0 = 1.f / l0, inv1 = 1.f / l1;
    float* out0 = out + (size_t)(b * S_ + q0 + r0) * D_ + hoff;
    float* out1 = out + (size_t)(b * S_ + q0 + r0 + 8) * D_ + hoff;
#pragma unroll
    for (int nt = 0; nt < 8; nt++) {
        int c = nt * 8 + 2 * t;
        float2 v0, v1;
        v0.x = __uint_as_float(f2tf32(acc_o[nt][0] * inv0));
        v0.y = __uint_as_float(f2tf32(acc_o[nt][1] * inv0));
        v1.x = __uint_as_float(f2tf32(acc_o[nt][2] * inv1));
        v1.y = __uint_as_float(f2tf32(acc_o[nt][3] * inv1));
        *(float2*)(out0 + c) = v0;
        *(float2*)(out1 + c) = v1;
    }
}

// ---------------------------------------------------------------------------
extern "C" void kernel_launch(void* const* d_in, const int* in_sizes, int n_in,
                              void* d_out, int out_size)
{
    const float* x      = (const float*)d_in[0];
    const float* w_qkv  = (const float*)d_in[1];
    const float* b_qkv  = (const float*)d_in[2];
    const float* w_proj = (const float*)d_in[3];
    const float* b_proj = (const float*)d_in[4];
    float* out = (float*)d_out;

    float *qkv_p, *attn_p, *x_p, *wq_p, *wp_p;
    cudaGetSymbolAddress((void**)&qkv_p,  g_qkv);
    cudaGetSymbolAddress((void**)&attn_p, g_attn);
    cudaGetSymbolAddress((void**)&x_p,    g_x);
    cudaGetSymbolAddress((void**)&wq_p,   g_wq);
    cudaGetSymbolAddress((void**)&wp_p,   g_wp);

    static bool attr_set = false;
    if (!attr_set) {
        cudaFuncSetAttribute(gemm_mma, cudaFuncAttributeMaxDynamicSharedMemorySize,
                             GEMM_SMEM);
        cudaFuncSetAttribute(attn_mma, cudaFuncAttributeMaxDynamicSharedMemorySize,
                             ATTN_SMEM);
        attr_set = true;
    }

    const int n4x = M_ * D_ / 4;
    const int n4q = D_ * 3 * D_ / 4;
    const int n4p = D_ * D_ / 4;
    round_tf32<<<(n4x + 255) / 256, 256>>>((const float4*)x,      (float4*)x_p,  n4x);
    round_tf32<<<(n4q + 255) / 256, 256>>>((const float4*)w_qkv,  (float4*)wq_p, n4q);
    round_tf32<<<(n4p + 255) / 256, 256>>>((const float4*)w_proj, (float4*)wp_p, n4p);

    gemm_mma<<<dim3(3 * D_ / 128, M_ / 128), 256, GEMM_SMEM>>>(
        x_p, wq_p, b_qkv, qkv_p, 3 * D_, D_, 1);

    attn_mma<<<dim3(S_ / 64, B_ * H_), 128, ATTN_SMEM>>>(qkv_p, attn_p);

    gemm_mma<<<dim3(D_ / 128, M_ / 128), 256, GEMM_SMEM>>>(
        attn_p, wp_p, b_proj, out, D_, D_, 0);
}

// round 7
// speedup vs baseline: 4.4216x; 1.0291x over previous
#include <cuda_runtime.h>
#include <cstdint>
#include <math.h>

#define B_  4
#define S_  2048
#define D_  1024
#define H_  16
#define HD_ 64
#define M_  (B_ * S_)   // 8192

__device__ float g_qkv[(size_t)M_ * 3 * D_];   // [B*S, 3D], tf32-rounded
__device__ float g_attn[(size_t)M_ * D_];      // [B*S, D],  tf32-rounded
__device__ float g_x  [(size_t)M_ * D_];       // rounded x
__device__ float g_wq [(size_t)D_ * 3 * D_];   // rounded w_qkv
__device__ float g_wp [(size_t)D_ * D_];       // rounded w_proj

__device__ __forceinline__ uint32_t f2tf32(float f) {
    uint32_t u;
    asm("cvt.rna.tf32.f32 %0, %1;" : "=r"(u) : "f"(f));
    return u;
}

__device__ __forceinline__ void mma_tf32(float& d0, float& d1, float& d2, float& d3,
                                         uint32_t a0, uint32_t a1, uint32_t a2, uint32_t a3,
                                         uint32_t b0, uint32_t b1) {
    asm volatile(
        "mma.sync.aligned.m16n8k8.row.col.f32.tf32.tf32.f32 "
        "{%0,%1,%2,%3}, {%4,%5,%6,%7}, {%8,%9}, {%0,%1,%2,%3};"
        : "+f"(d0), "+f"(d1), "+f"(d2), "+f"(d3)
        : "r"(a0), "r"(a1), "r"(a2), "r"(a3), "r"(b0), "r"(b1));
}

__device__ __forceinline__ uint32_t smem_u32(const void* p) {
    uint32_t a;
    asm("{ .reg .u64 t; cvta.to.shared.u64 t, %1; cvt.u32.u64 %0, t; }"
        : "=r"(a) : "l"(p));
    return a;
}

__device__ __forceinline__ void ldsm_x4(uint32_t& r0, uint32_t& r1,
                                        uint32_t& r2, uint32_t& r3, uint32_t addr) {
    asm volatile("ldmatrix.sync.aligned.m8n8.x4.shared.b16 {%0,%1,%2,%3}, [%4];"
                 : "=r"(r0), "=r"(r1), "=r"(r2), "=r"(r3) : "r"(addr));
}

__device__ __forceinline__ void cp16(uint32_t dst, const void* src) {
    asm volatile("cp.async.cg.shared.global [%0], [%1], 16;"
                 :: "r"(dst), "l"(src) : "memory");
}
__device__ __forceinline__ void cp_commit() {
    asm volatile("cp.async.commit_group;" ::: "memory");
}
__device__ __forceinline__ void cp_wait1() {
    asm volatile("cp.async.wait_group 1;" ::: "memory");
}
__device__ __forceinline__ void cp_wait0() {
    asm volatile("cp.async.wait_group 0;" ::: "memory");
}

// ---------------------------------------------------------------------------
__global__ void round_tf32(const float4* __restrict__ src, float4* __restrict__ dst,
                           int n4)
{
    int i = blockIdx.x * blockDim.x + threadIdx.x;
    if (i < n4) {
        float4 v = src[i];
        uint4 u;
        u.x = f2tf32(v.x); u.y = f2tf32(v.y);
        u.z = f2tf32(v.z); u.w = f2tf32(v.w);
        *(uint4*)&dst[i] = u;
    }
}

// ---------------------------------------------------------------------------
// TF32 mma.sync GEMM + bias (unchanged from passing R6)
// ---------------------------------------------------------------------------
#define AS_STRIDE 36
#define BS_STRIDE 136
#define AS_TILE   (128 * AS_STRIDE)
#define BS_TILE   (32 * BS_STRIDE)
#define GEMM_SMEM (3 * (AS_TILE + BS_TILE) * 4)   // 107520 B

__global__ __launch_bounds__(256) void gemm_mma(
    const float* __restrict__ A, const float* __restrict__ W,
    const float* __restrict__ bias, float* __restrict__ C,
    int N, int K, int round_out)
{
    extern __shared__ __align__(16) float sm[];
    const uint32_t sAaddr = smem_u32(sm);
    const uint32_t sBaddr = sAaddr + 3u * AS_TILE * 4u;

    const int tid = threadIdx.x;
    const int lane = tid & 31, wid = tid >> 5;
    const int wm = wid & 1, wn = wid >> 1;
    const int bx = blockIdx.x, by = blockIdx.y;
    const int g = lane >> 2, t = lane & 3;

    const int arow = tid >> 3;
    const int acol = (tid & 7) << 2;
    const int brow = tid >> 5;
    const int bcol = (tid & 31) << 2;
    const float* Ag = A + (size_t)(by * 128 + arow) * K + acol;
    const float* Wg = W + (size_t)brow * N + bx * 128 + bcol;

    uint32_t aoff[4], boff[4];
#pragma unroll
    for (int i = 0; i < 4; i++) {
        aoff[i] = (uint32_t)(((arow + i * 32) * AS_STRIDE + acol) * 4);
        boff[i] = (uint32_t)(((brow + i * 8) * BS_STRIDE + bcol) * 4);
    }

    uint32_t a_lm[4];
#pragma unroll
    for (int mt = 0; mt < 4; mt++)
        a_lm[mt] = (uint32_t)(((wm * 64 + mt * 16 + (lane & 15)) * AS_STRIDE
                               + (lane >> 4) * 4) * 4);

    const int nstages = K >> 5;

    auto issue = [&](int s, int buf) {
        const uint32_t dA = sAaddr + (uint32_t)buf * (AS_TILE * 4u);
        const uint32_t dB = sBaddr + (uint32_t)buf * (BS_TILE * 4u);
        const float* a_ = Ag + (s << 5);
        const float* w_ = Wg + (size_t)(s << 5) * N;
#pragma unroll
        for (int i = 0; i < 4; i++) {
            cp16(dA + aoff[i], a_ + (size_t)i * 32 * K);
            cp16(dB + boff[i], w_ + (size_t)i * 8 * N);
        }
        cp_commit();
    };

    issue(0, 0);
    issue(1, 1);

    float acc[4][4][4];
#pragma unroll
    for (int mt = 0; mt < 4; mt++)
#pragma unroll
        for (int nt = 0; nt < 4; nt++)
#pragma unroll
            for (int r = 0; r < 4; r++) acc[mt][nt][r] = 0.f;

    cp_wait1();
    __syncthreads();

    const uint32_t* smu = (const uint32_t*)sm;

    for (int s = 0; s < nstages; s++) {
        const int buf = s % 3;
        const uint32_t cAaddr = sAaddr + (uint32_t)buf * (AS_TILE * 4u);
        const uint32_t* cB = smu + 3 * AS_TILE + buf * BS_TILE;

#pragma unroll
        for (int ks = 0; ks < 4; ks++) {
            const int k0 = ks << 3;
            uint32_t af[4][4], bf[4][2];
#pragma unroll
            for (int mt = 0; mt < 4; mt++)
                ldsm_x4(af[mt][0], af[mt][1], af[mt][2], af[mt][3],
                        cAaddr + a_lm[mt] + (uint32_t)(k0 * 4));
#pragma unroll
            for (int nt = 0; nt < 4; nt++) {
                const uint32_t* base = cB + (k0 + t) * BS_STRIDE + wn * 32 + nt * 8 + g;
                bf[nt][0] = base[0];
                bf[nt][1] = base[4 * BS_STRIDE];
            }
#pragma unroll
            for (int mt = 0; mt < 4; mt++)
#pragma unroll
                for (int nt = 0; nt < 4; nt++)
                    mma_tf32(acc[mt][nt][0], acc[mt][nt][1], acc[mt][nt][2], acc[mt][nt][3],
                             af[mt][0], af[mt][1], af[mt][2], af[mt][3],
                             bf[nt][0], bf[nt][1]);
        }

        if (s + 2 < nstages) {
            issue(s + 2, (s + 2) % 3);
            cp_wait1();
        } else {
            cp_wait0();
        }
        __syncthreads();
    }

#pragma unroll
    for (int nt = 0; nt < 4; nt++) {
        const int c = bx * 128 + wn * 32 + nt * 8 + 2 * t;
        const float bx0 = bias[c], bx1 = bias[c + 1];
#pragma unroll
        for (int mt = 0; mt < 4; mt++) {
            const int r0 = by * 128 + wm * 64 + mt * 16 + g;
            float v00 = acc[mt][nt][0] + bx0, v01 = acc[mt][nt][1] + bx1;
            float v10 = acc[mt][nt][2] + bx0, v11 = acc[mt][nt][3] + bx1;
            if (round_out) {
                v00 = __uint_as_float(f2tf32(v00));
                v01 = __uint_as_float(f2tf32(v01));
                v10 = __uint_as_float(f2tf32(v10));
                v11 = __uint_as_float(f2tf32(v11));
            }
            *(float2*)(C + (size_t)r0 * N + c)       = make_float2(v00, v01);
            *(float2*)(C + (size_t)(r0 + 8) * N + c) = make_float2(v10, v11);
        }
    }
}

// ---------------------------------------------------------------------------
// TF32 mma.sync flash attention, R7: 256 threads / 128 q-rows per CTA
// (halves KV fill per unit mma), ldsm_x4 K B-frags (pairs nt,nt+1),
// shuffle-free PV via V-row permutation. Per-warp numerics identical to R6.
// ---------------------------------------------------------------------------
#define KS_ST 68
#define VS_ST 72
#define ATTN_SMEM ((2 * 64 * KS_ST + 2 * 64 * VS_ST) * 4)   // 71680 B

__global__ __launch_bounds__(256) void attn_mma(const float* __restrict__ qkv,
                                                float* __restrict__ out)
{
    extern __shared__ __align__(16) uint32_t smu[];
    uint32_t* sKu = smu;                       // [2][64*KS_ST]; also Q staging [128][KS_ST]
    uint32_t* sVu = smu + 2 * 64 * KS_ST;      // [2][64*VS_ST]
    const uint32_t sKaddr = smem_u32(sKu);
    const uint32_t sVaddr = smem_u32(sVu);

    const int tid = threadIdx.x;
    const int lane = tid & 31;
    const int w = tid >> 5;              // 0..7 warps
    const int g = lane >> 2;
    const int t = lane & 3;
    const int bh = blockIdx.y;
    const int b = bh >> 4, h = bh & 15;
    const int q0 = blockIdx.x * 128;

    const size_t row3D = 3 * (size_t)D_;
    const size_t hoff = (size_t)h * HD_;

    // KV fill mapping (256 threads, 64 rows x 64 cols per tile)
    const int krow = tid >> 4;            // 0..15
    const int kcol = (tid & 15) << 2;     // 0..60
    const int inner = krow & 7;
    const int pinner = (inner & 1) ? (inner >> 1) + 4 : (inner >> 1);
    const int vrow0 = (krow & 8) + pinner;   // + i*16 per chunk

    // ldmatrix x4 per-lane offset for K B-frags (matrices: nt rows 0-7 col 0,
    // nt rows 0-7 col 4, nt+1 rows 0-7 col 0, nt+1 rows 0-7 col 4)
    const int m4 = lane >> 3;
    const uint32_t k_lm4 = (uint32_t)(((((m4 & 2) << 2) + (lane & 7)) * KS_ST
                                       + (m4 & 1) * 4) * 4);

    // ---- stage Q (128 rows) through sKu region; scale by 1/8 (exact) ----
#pragma unroll
    for (int i = 0; i < 8; i++) {
        int idx = tid + i * 256;
        int r = idx >> 4, c = (idx & 15) << 2;
        float4 v = *(const float4*)(qkv + (size_t)(b * S_ + q0 + r) * row3D + hoff + c);
        uint4 u;
        u.x = __float_as_uint(v.x * 0.125f); u.y = __float_as_uint(v.y * 0.125f);
        u.z = __float_as_uint(v.z * 0.125f); u.w = __float_as_uint(v.w * 0.125f);
        *(uint4*)&sKu[r * KS_ST + c] = u;
    }
    __syncthreads();

    const int r0 = w * 16 + g;
    uint32_t aq[8][4];
#pragma unroll
    for (int j = 0; j < 8; j++) {
        aq[j][0] = sKu[r0 * KS_ST + 8 * j + t];
        aq[j][1] = sKu[(r0 + 8) * KS_ST + 8 * j + t];
        aq[j][2] = sKu[r0 * KS_ST + 8 * j + t + 4];
        aq[j][3] = sKu[(r0 + 8) * KS_ST + 8 * j + t + 4];
    }
    __syncthreads();

    const float* kvbase = qkv + (size_t)(b * S_ + krow) * row3D + hoff + kcol;
    auto issue = [&](int tile, int buf) {
        const float* src = kvbase + (size_t)tile * 64 * row3D;
        const uint32_t dK = sKaddr + (uint32_t)buf * (64 * KS_ST * 4u);
        const uint32_t dV = sVaddr + (uint32_t)buf * (64 * VS_ST * 4u);
#pragma unroll
        for (int i = 0; i < 4; i++) {
            cp16(dK + (uint32_t)(((krow + i * 16) * KS_ST + kcol) * 4),
                 src + (size_t)i * 16 * row3D + D_);
            cp16(dV + (uint32_t)(((vrow0 + i * 16) * VS_ST + kcol) * 4),
                 src + (size_t)i * 16 * row3D + 2 * D_);
        }
        cp_commit();
    };

    issue(0, 0);

    float m0 = -3.0e38f, m1 = -3.0e38f, l0 = 0.f, l1 = 0.f;
    float acc_o[8][4];
#pragma unroll
    for (int nt = 0; nt < 8; nt++)
#pragma unroll
        for (int r = 0; r < 4; r++) acc_o[nt][r] = 0.f;

    const int ntiles = S_ / 64;
    for (int i = 0; i < ntiles; i++) {
        const int buf = i & 1;
        if (i + 1 < ntiles) {
            issue(i + 1, buf ^ 1);
            cp_wait1();
        } else {
            cp_wait0();
        }
        __syncthreads();

        const uint32_t cKaddr = sKaddr + (uint32_t)buf * (64 * KS_ST * 4u);
        const uint32_t* cV = sVu + buf * (64 * VS_ST);

        // ---- S = Q @ K^T (ldsm_x4 B-frags, two nt blocks per load) ----
        float acc_s[8][4];
#pragma unroll
        for (int nt = 0; nt < 8; nt++)
#pragma unroll
            for (int r = 0; r < 4; r++) acc_s[nt][r] = 0.f;

#pragma unroll
        for (int j = 0; j < 8; j++) {
#pragma unroll
            for (int ntp = 0; ntp < 4; ntp++) {
                uint32_t b0, b1, b2, b3;
                ldsm_x4(b0, b1, b2, b3,
                        cKaddr + k_lm4 + (uint32_t)(((ntp * 16) * KS_ST + 8 * j) * 4));
                mma_tf32(acc_s[2*ntp][0], acc_s[2*ntp][1], acc_s[2*ntp][2], acc_s[2*ntp][3],
                         aq[j][0], aq[j][1], aq[j][2], aq[j][3], b0, b1);
                mma_tf32(acc_s[2*ntp+1][0], acc_s[2*ntp+1][1], acc_s[2*ntp+1][2], acc_s[2*ntp+1][3],
                         aq[j][0], aq[j][1], aq[j][2], aq[j][3], b2, b3);
            }
        }

        // ---- online softmax ----
        float mx0 = -3.0e38f, mx1 = -3.0e38f;
#pragma unroll
        for (int nt = 0; nt < 8; nt++) {
            mx0 = fmaxf(mx0, fmaxf(acc_s[nt][0], acc_s[nt][1]));
            mx1 = fmaxf(mx1, fmaxf(acc_s[nt][2], acc_s[nt][3]));
        }
        mx0 = fmaxf(mx0, __shfl_xor_sync(0xffffffffu, mx0, 1));
        mx0 = fmaxf(mx0, __shfl_xor_sync(0xffffffffu, mx0, 2));
        mx1 = fmaxf(mx1, __shfl_xor_sync(0xffffffffu, mx1, 1));
        mx1 = fmaxf(mx1, __shfl_xor_sync(0xffffffffu, mx1, 2));

        float mn0 = fmaxf(m0, mx0), mn1 = fmaxf(m1, mx1);
        float al0 = __expf(m0 - mn0), al1 = __expf(m1 - mn1);
        m0 = mn0; m1 = mn1;

        uint32_t ps[8][4];
        float sum0 = 0.f, sum1 = 0.f;
#pragma unroll
        for (int nt = 0; nt < 8; nt++) {
            uint32_t u;
            u = f2tf32(__expf(acc_s[nt][0] - mn0)); ps[nt][0] = u; sum0 += __uint_as_float(u);
            u = f2tf32(__expf(acc_s[nt][1] - mn0)); ps[nt][1] = u; sum0 += __uint_as_float(u);
            u = f2tf32(__expf(acc_s[nt][2] - mn1)); ps[nt][2] = u; sum1 += __uint_as_float(u);
            u = f2tf32(__expf(acc_s[nt][3] - mn1)); ps[nt][3] = u; sum1 += __uint_as_float(u);
        }
        sum0 += __shfl_xor_sync(0xffffffffu, sum0, 1);
        sum0 += __shfl_xor_sync(0xffffffffu, sum0, 2);
        sum1 += __shfl_xor_sync(0xffffffffu, sum1, 1);
        sum1 += __shfl_xor_sync(0xffffffffu, sum1, 2);
        l0 = l0 * al0 + sum0;
        l1 = l1 * al1 + sum1;

#pragma unroll
        for (int nt = 0; nt < 8; nt++) {
            acc_o[nt][0] *= al0; acc_o[nt][1] *= al0;
            acc_o[nt][2] *= al1; acc_o[nt][3] *= al1;
        }

        // ---- O += P @ V (shuffle-free: V rows permuted, A = (c0,c2,c1,c3)) ----
#pragma unroll
        for (int j = 0; j < 8; j++) {
            const uint32_t a0 = ps[j][0], a1 = ps[j][2];
            const uint32_t a2 = ps[j][1], a3 = ps[j][3];
#pragma unroll
            for (int nt = 0; nt < 8; nt++) {
                const uint32_t* vb = &cV[(8 * j + t) * VS_ST + nt * 8 + g];
                mma_tf32(acc_o[nt][0], acc_o[nt][1], acc_o[nt][2], acc_o[nt][3],
                         a0, a1, a2, a3,
                         vb[0], vb[4 * VS_ST]);
            }
        }
        __syncthreads();
    }

    // ---- epilogue (tf32-rounded for proj GEMM) ----
    const float inv0 = 1.f / l0, inv1 = 1.f / l1;
    float* out0 = out + (size_t)(b * S_ + q0 + r0) * D_ + hoff;
    float* out1 = out + (size_t)(b * S_ + q0 + r0 + 8) * D_ + hoff;
#pragma unroll
    for (int nt = 0; nt < 8; nt++) {
        int c = nt * 8 + 2 * t;
        float2 v0, v1;
        v0.x = __uint_as_float(f2tf32(acc_o[nt][0] * inv0));
        v0.y = __uint_as_float(f2tf32(acc_o[nt][1] * inv0));
        v1.x = __uint_as_float(f2tf32(acc_o[nt][2] * inv1));
        v1.y = __uint_as_float(f2tf32(acc_o[nt][3] * inv1));
        *(float2*)(out0 + c) = v0;
        *(float2*)(out1 + c) = v1;
    }
}

// ---------------------------------------------------------------------------
extern "C" void kernel_launch(void* const* d_in, const int* in_sizes, int n_in,
                              void* d_out, int out_size)
{
    const float* x      = (const float*)d_in[0];
    const float* w_qkv  = (const float*)d_in[1];
    const float* b_qkv  = (const float*)d_in[2];
    const float* w_proj = (const float*)d_in[3];
    const float* b_proj = (const float*)d_in[4];
    float* out = (float*)d_out;

    float *qkv_p, *attn_p, *x_p, *wq_p, *wp_p;
    cudaGetSymbolAddress((void**)&qkv_p,  g_qkv);
    cudaGetSymbolAddress((void**)&attn_p, g_attn);
    cudaGetSymbolAddress((void**)&x_p,    g_x);
    cudaGetSymbolAddress((void**)&wq_p,   g_wq);
    cudaGetSymbolAddress((void**)&wp_p,   g_wp);

    static bool attr_set = false;
    if (!attr_set) {
        cudaFuncSetAttribute(gemm_mma, cudaFuncAttributeMaxDynamicSharedMemorySize,
                             GEMM_SMEM);
        cudaFuncSetAttribute(attn_mma, cudaFuncAttributeMaxDynamicSharedMemorySize,
                             ATTN_SMEM);
        attr_set = true;
    }

    const int n4x = M_ * D_ / 4;
    const int n4q = D_ * 3 * D_ / 4;
    const int n4p = D_ * D_ / 4;
    round_tf32<<<(n4x + 255) / 256, 256>>>((const float4*)x,      (float4*)x_p,  n4x);
    round_tf32<<<(n4q + 255) / 256, 256>>>((const float4*)w_qkv,  (float4*)wq_p, n4q);
    round_tf32<<<(n4p + 255) / 256, 256>>>((const float4*)w_proj, (float4*)wp_p, n4p);

    gemm_mma<<<dim3(3 * D_ / 128, M_ / 128), 256, GEMM_SMEM>>>(
        x_p, wq_p, b_qkv, qkv_p, 3 * D_, D_, 1);

    attn_mma<<<dim3(S_ / 128, B_ * H_), 256, ATTN_SMEM>>>(qkv_p, attn_p);

    gemm_mma<<<dim3(D_ / 128, M_ / 128), 256, GEMM_SMEM>>>(
        attn_p, wp_p, b_proj, out, D_, D_, 0);
}